// round 10
// baseline (speedup 1.0000x reference)
#include <cuda_runtime.h>
#include <cuda_bf16.h>
#include <math.h>
#include <stdint.h>

#define B_ 2
#define N_ 2048
#define C_ 1024
#define H_ 16
#define D_ 64
#define QSCALE_ (0.125f * 1.4426950408889634f)   // SCALE * log2(e), folded into q
#define SHIFT2_ 11.541560327111708f              // 8 * log2(e)

// ---------------------------------------------------------------------------
// Scratch (allocation-free): all operands as separate hi/lo bf16 arrays
// ---------------------------------------------------------------------------
__device__ __nv_bfloat16 g_qh[(size_t)B_ * H_ * N_ * D_];
__device__ __nv_bfloat16 g_ql[(size_t)B_ * H_ * N_ * D_];
__device__ __nv_bfloat16 g_kh[(size_t)B_ * H_ * N_ * D_];
__device__ __nv_bfloat16 g_kl[(size_t)B_ * H_ * N_ * D_];
__device__ __nv_bfloat16 g_vh[(size_t)B_ * H_ * N_ * D_];
__device__ __nv_bfloat16 g_vl[(size_t)B_ * H_ * N_ * D_];
__device__ __nv_bfloat16 g_maskb[(size_t)N_ * N_];

__device__ __nv_bfloat16 g_xh [(size_t)(B_ * N_) * C_];
__device__ __nv_bfloat16 g_xl [(size_t)(B_ * N_) * C_];
__device__ __nv_bfloat16 g_wqh[(size_t)(3 * C_) * C_];
__device__ __nv_bfloat16 g_wql[(size_t)(3 * C_) * C_];
__device__ __nv_bfloat16 g_th [(size_t)(B_ * N_) * C_];
__device__ __nv_bfloat16 g_tl [(size_t)(B_ * N_) * C_];
__device__ __nv_bfloat16 g_wph[(size_t)C_ * C_];
__device__ __nv_bfloat16 g_wpl[(size_t)C_ * C_];

// ---------------------------------------------------------------------------
// PTX helpers
// ---------------------------------------------------------------------------
__device__ __forceinline__ uint32_t smem_u32(const void* p) {
    uint32_t a;
    asm("{ .reg .u64 t; cvta.to.shared.u64 t, %1; cvt.u32.u64 %0, t; }" : "=r"(a) : "l"(p));
    return a;
}
__device__ __forceinline__ void cp16(uint32_t dst, const void* src) {
    asm volatile("cp.async.cg.shared.global [%0], [%1], 16;" :: "r"(dst), "l"(src));
}
__device__ __forceinline__ void cp_commit() {
    asm volatile("cp.async.commit_group;");
}
__device__ __forceinline__ void cp_wait0() {
    asm volatile("cp.async.wait_group 0;");
}
__device__ __forceinline__ void cp_wait1() {
    asm volatile("cp.async.wait_group 1;");
}
__device__ __forceinline__ void cp_wait2() {
    asm volatile("cp.async.wait_group 2;");
}
__device__ __forceinline__ void ldsm4(uint32_t* r, uint32_t a) {
    asm volatile("ldmatrix.sync.aligned.m8n8.x4.shared.b16 {%0,%1,%2,%3}, [%4];"
                 : "=r"(r[0]), "=r"(r[1]), "=r"(r[2]), "=r"(r[3]) : "r"(a));
}
__device__ __forceinline__ void ldsm4t(uint32_t* r, uint32_t a) {
    asm volatile("ldmatrix.sync.aligned.m8n8.x4.trans.shared.b16 {%0,%1,%2,%3}, [%4];"
                 : "=r"(r[0]), "=r"(r[1]), "=r"(r[2]), "=r"(r[3]) : "r"(a));
}
__device__ __forceinline__ void mma16816(float* c, const uint32_t* a, uint32_t b0, uint32_t b1) {
    asm volatile(
        "mma.sync.aligned.m16n8k16.row.col.f32.bf16.bf16.f32 "
        "{%0,%1,%2,%3}, {%4,%5,%6,%7}, {%8,%9}, {%0,%1,%2,%3};"
        : "+f"(c[0]), "+f"(c[1]), "+f"(c[2]), "+f"(c[3])
        : "r"(a[0]), "r"(a[1]), "r"(a[2]), "r"(a[3]), "r"(b0), "r"(b1));
}
__device__ __forceinline__ float fexp2(float x) {
    float r;
    asm("ex2.approx.f32 %0, %1;" : "=f"(r) : "f"(x));
    return r;
}
__device__ __forceinline__ void split_pack(float a, float b, uint32_t& hp, uint32_t& lp) {
    __nv_bfloat16 ha = __float2bfloat16(a), hb = __float2bfloat16(b);
    __nv_bfloat16 la = __float2bfloat16(a - __bfloat162float(ha));
    __nv_bfloat16 lb = __float2bfloat16(b - __bfloat162float(hb));
    __nv_bfloat162 hv = {ha, hb}, lv = {la, lb};
    hp = *(uint32_t*)&hv;
    lp = *(uint32_t*)&lv;
}

// ---------------------------------------------------------------------------
// Fused preprocessing: x/w_qkv/w_proj hi/lo splits + mask bf16 conversion,
// one launch, one quad (float4) per thread.
// ---------------------------------------------------------------------------
#define QX  (B_ * N_ * C_ / 4)          // 1048576
#define QWQ (3 * C_ * C_ / 4)           //  786432
#define QWP (C_ * C_ / 4)               //  262144
#define QMK (N_ * N_ / 4)               // 1048576
#define QTOT (QX + QWQ + QWP + QMK)     // 3145728

__device__ __forceinline__ void split_quad(const float* __restrict__ src,
                                           __nv_bfloat16* __restrict__ dh,
                                           __nv_bfloat16* __restrict__ dl, int i4) {
    float4 a = ((const float4*)src)[i4];
    __nv_bfloat16 h0 = __float2bfloat16(a.x), h1 = __float2bfloat16(a.y);
    __nv_bfloat16 h2 = __float2bfloat16(a.z), h3 = __float2bfloat16(a.w);
    __nv_bfloat16 l0 = __float2bfloat16(a.x - __bfloat162float(h0));
    __nv_bfloat16 l1 = __float2bfloat16(a.y - __bfloat162float(h1));
    __nv_bfloat16 l2 = __float2bfloat16(a.z - __bfloat162float(h2));
    __nv_bfloat16 l3 = __float2bfloat16(a.w - __bfloat162float(h3));
    __nv_bfloat162 hA = {h0, h1}, hB = {h2, h3};
    __nv_bfloat162 lA = {l0, l1}, lB = {l2, l3};
    ((__nv_bfloat162*)dh)[2 * i4]     = hA;
    ((__nv_bfloat162*)dh)[2 * i4 + 1] = hB;
    ((__nv_bfloat162*)dl)[2 * i4]     = lA;
    ((__nv_bfloat162*)dl)[2 * i4 + 1] = lB;
}

__global__ __launch_bounds__(256) void preproc_kernel(const float* __restrict__ x,
                                                      const float* __restrict__ wqkv,
                                                      const float* __restrict__ wproj,
                                                      const float* __restrict__ mask) {
    int i = blockIdx.x * 256 + threadIdx.x;
    if (i < QX) {
        split_quad(x, g_xh, g_xl, i);
    } else if (i < QX + QWQ) {
        split_quad(wqkv, g_wqh, g_wql, i - QX);
    } else if (i < QX + QWQ + QWP) {
        split_quad(wproj, g_wph, g_wpl, i - QX - QWQ);
    } else {
        int j = i - QX - QWQ - QWP;
        float4 v = ((const float4*)mask)[j];
        __nv_bfloat162 p0 = {__float2bfloat16(v.x), __float2bfloat16(v.y)};
        __nv_bfloat162 p1 = {__float2bfloat16(v.z), __float2bfloat16(v.w)};
        ((__nv_bfloat162*)g_maskb)[2 * j]     = p0;
        ((__nv_bfloat162*)g_maskb)[2 * j + 1] = p1;
    }
}

// ---------------------------------------------------------------------------
// mma.sync GEMM, in-register 3-term split, CTA 128x128, warp 64x32,
// 4-STAGE cp.async pipeline with BK=16 stages (prefetch distance 3).
// mode 0: split-scatter into g_{q,k,v}{h,l} (q pre-scaled by QSCALE_).
// mode 1: out = D + bias.
// ---------------------------------------------------------------------------
#define P16 24                           // smem pitch (bf16) for 16-wide stage tiles
#define GK 1024
#define MITERS16 (GK / 16)               // 64
#define ST_SZ (128 * P16)                // per-tile elems per stage = 3072
#define T16_AH 0
#define T16_AL ST_SZ
#define T16_BH (2 * ST_SZ)
#define T16_BL (3 * ST_SZ)
#define STAGE_ELEMS (4 * ST_SZ)          // 12288 elems = 24576 B
#define NSTAGE 4
#define MM_SMEM (NSTAGE * STAGE_ELEMS * 2)  // 98304 B -> 2 CTAs/SM

__global__ __launch_bounds__(256, 2) void mm_mma_kernel(const __nv_bfloat16* __restrict__ Ah,
                                                        const __nv_bfloat16* __restrict__ Al,
                                                        const __nv_bfloat16* __restrict__ Bh,
                                                        const __nv_bfloat16* __restrict__ Bl,
                                                        int mode,
                                                        const float* __restrict__ bias,
                                                        float* __restrict__ outp) {
    extern __shared__ __nv_bfloat16 smb[];

    const int tid = threadIdx.x;
    const int wid = tid >> 5;
    const int lane = tid & 31;
    const int brow = blockIdx.y * 128;
    const int bcol = blockIdx.x * 128;
    const int mbase = (wid >> 2) * 64;
    const int nbase = (wid & 3) * 32;

    const uint32_t sbase = smem_u32(smb);

    const int lr = tid >> 1;             // 0..127
    const int lch = tid & 1;             // 16B chunk within the 32B row

    auto load_stage = [&](int kt, int stg) {
        const int k0 = kt * 16;
        const size_t goA = (size_t)(brow + lr) * GK + k0 + lch * 8;
        const size_t goB = (size_t)(bcol + lr) * GK + k0 + lch * 8;
        uint32_t sb = sbase + stg * (STAGE_ELEMS * 2) + (lr * P16) * 2 + lch * 16;
        cp16(sb + T16_AH * 2, Ah + goA);
        cp16(sb + T16_AL * 2, Al + goA);
        cp16(sb + T16_BH * 2, Bh + goB);
        cp16(sb + T16_BL * 2, Bl + goB);
        cp_commit();
    };

    float acc[4][4][4] = {};

    load_stage(0, 0);
    load_stage(1, 1);
    load_stage(2, 2);

    for (int kt = 0; kt < MITERS16; kt++) {
        cp_wait2();                      // stage kt complete (groups retire in order)
        __syncthreads();                 // all warps done reading buffer (kt-1)&3
        if (kt + 3 < MITERS16) {
            load_stage(kt + 3, (kt + 3) & 3);   // overwrites buffer (kt-1)&3
        } else {
            cp_commit();                 // empty group keeps wait arithmetic uniform
        }

        const uint32_t sb = sbase + (kt & 3) * (STAGE_ELEMS * 2);
        uint32_t bh[2][4], bl[2][4];
#pragma unroll
        for (int j = 0; j < 2; j++) {
            int row = nbase + j * 16 + ((lane >> 4) & 1) * 8 + (lane & 7);
            int col = ((lane >> 3) & 1) * 8;
            uint32_t ba = sb + (row * P16 + col) * 2;
            ldsm4(bh[j], ba + T16_BH * 2);
            ldsm4(bl[j], ba + T16_BL * 2);
        }
#pragma unroll
        for (int i = 0; i < 4; i++) {
            uint32_t aa = sb + ((mbase + i * 16 + (lane & 15)) * P16 + (lane >> 4) * 8) * 2;
            uint32_t ah[4], al[4];
            ldsm4(ah, aa + T16_AH * 2);
            ldsm4(al, aa + T16_AL * 2);
#pragma unroll
            for (int j = 0; j < 2; j++) {
                mma16816(acc[i][2 * j],     ah, bh[j][0], bh[j][1]);
                mma16816(acc[i][2 * j],     al, bh[j][0], bh[j][1]);
                mma16816(acc[i][2 * j],     ah, bl[j][0], bl[j][1]);
                mma16816(acc[i][2 * j + 1], ah, bh[j][2], bh[j][3]);
                mma16816(acc[i][2 * j + 1], al, bh[j][2], bh[j][3]);
                mma16816(acc[i][2 * j + 1], ah, bl[j][2], bl[j][3]);
            }
        }
    }

    const int r0 = brow + mbase + (lane >> 2);
    const int cq = (lane & 3) * 2;
#pragma unroll
    for (int i = 0; i < 4; i++) {
#pragma unroll
        for (int jj = 0; jj < 4; jj++) {
            const float* c = acc[i][jj];
            int gc = bcol + nbase + jj * 8 + cq;
#pragma unroll
            for (int hrow = 0; hrow < 2; hrow++) {
                int gi = r0 + i * 16 + hrow * 8;
                float vx = c[hrow * 2 + 0], vy = c[hrow * 2 + 1];
                if (mode == 0) {
                    int bb = gi >> 11;
                    int nseq = gi & (N_ - 1);
                    int three = gc >> 10;
                    int h = (gc >> 6) & (H_ - 1);
                    int d = gc & (D_ - 1);
                    if (three == 0) { vx *= QSCALE_; vy *= QSCALE_; }   // fold scale*log2e into q
                    uint32_t hp, lp;
                    split_pack(vx, vy, hp, lp);
                    __nv_bfloat16 *hd, *ld;
                    if (three == 0)      { hd = g_qh; ld = g_ql; }
                    else if (three == 1) { hd = g_kh; ld = g_kl; }
                    else                 { hd = g_vh; ld = g_vl; }
                    size_t off = (((size_t)bb * H_ + h) * N_ + nseq) * D_ + d;
                    *(uint32_t*)(hd + off) = hp;
                    *(uint32_t*)(ld + off) = lp;
                } else {
                    float2 val = {vx + bias[gc], vy + bias[gc + 1]};
                    *(float2*)&outp[(size_t)gi * C_ + gc] = val;
                }
            }
        }
    }
}

// ---------------------------------------------------------------------------
// Flash attention on mma.sync, MULTIPLICATIVE bf16 mask, 3-term splits,
// fixed-shift base-2 softmax: P = 2^(S'·mask - SHIFT2_), S' = QK with q
// pre-scaled by 0.125·log2e. Row sums accumulated per-lane, reduced once.
// ---------------------------------------------------------------------------
#define QT 128
#define KT 64
#define VP 72
#define A_QH 0
#define A_QL (QT * VP * 2)
#define A_BUF (2 * QT * VP * 2)
#define A_KH 0
#define A_KL (KT * VP * 2)
#define A_VH (2 * KT * VP * 2)
#define A_VL (3 * KT * VP * 2)
#define A_MS (4 * KT * VP * 2)
#define A_BUFSZ (4 * KT * VP * 2 + QT * VP * 2)   // 55296
#define ATT2_SMEM (A_BUF + 2 * A_BUFSZ)           // 147456

__global__ __launch_bounds__(256) void attn_mma_kernel(const __nv_bfloat16* __restrict__ maskb) {
    extern __shared__ char sm[];
    const uint32_t sb = smem_u32(sm);
    const int tid = threadIdx.x, wid = tid >> 5, lane = tid & 31;
    const int bh = blockIdx.y;
    const int row0 = blockIdx.x * QT;
    const int b = bh >> 4, h = bh & (H_ - 1);
    const size_t hoff = (size_t)bh * N_ * D_;
    const __nv_bfloat16 *qhp = g_qh + hoff, *qlp = g_ql + hoff;
    const __nv_bfloat16 *khp = g_kh + hoff, *klp = g_kl + hoff;
    const __nv_bfloat16 *vhp = g_vh + hoff, *vlp = g_vl + hoff;

    for (int idx = tid; idx < QT * 8; idx += 256) {
        int r = idx >> 3, cc = idx & 7;
        *(uint4*)(sm + A_QH + r * (VP * 2) + cc * 16) =
            *(const uint4*)(qhp + (size_t)(row0 + r) * D_ + cc * 8);
        *(uint4*)(sm + A_QL + r * (VP * 2) + cc * 16) =
            *(const uint4*)(qlp + (size_t)(row0 + r) * D_ + cc * 8);
    }
    __syncthreads();

    const int mrow0 = wid * 16;
    uint32_t qhf[4][4], qlf[4][4];
#pragma unroll
    for (int s = 0; s < 4; s++) {
        uint32_t ad = sb + A_QH + (mrow0 + (lane & 15)) * (VP * 2) + (s * 16 + (lane >> 4) * 8) * 2;
        ldsm4(qhf[s], ad);
        ldsm4(qlf[s], ad + (A_QL - A_QH));
    }

    auto prefetch = [&](int t, uint32_t bufb) {
        const int k0 = t * KT;
#pragma unroll
        for (int i = 0; i < 2; i++) {
            int idx = tid + i * 256;
            int r = idx >> 3, cc = idx & 7;
            uint32_t ro = r * (VP * 2) + cc * 16;
            size_t go = (size_t)(k0 + r) * D_ + cc * 8;
            cp16(bufb + A_KH + ro, khp + go);
            cp16(bufb + A_KL + ro, klp + go);
            cp16(bufb + A_VH + ro, vhp + go);
            cp16(bufb + A_VL + ro, vlp + go);
        }
#pragma unroll
        for (int i = 0; i < 4; i++) {
            int idx = tid + i * 256;
            int r = idx >> 3, cc = idx & 7;
            cp16(bufb + A_MS + r * (VP * 2) + cc * 16,
                 maskb + (size_t)(row0 + r) * N_ + k0 + cc * 8);
        }
        cp_commit();
    };

    float o_acc[8][4] = {};
    float lsum0 = 0.f, lsum1 = 0.f;
    const int q2 = (lane & 3) * 2;
    const int r0l = mrow0 + (lane >> 2);

    prefetch(0, sb + A_BUF);

    for (int t = 0; t < N_ / KT; t++) {
        const uint32_t bufb = sb + A_BUF + (t & 1) * A_BUFSZ;
        if (t + 1 < N_ / KT) {
            prefetch(t + 1, sb + A_BUF + ((t + 1) & 1) * A_BUFSZ);
            cp_wait1();
        } else {
            cp_wait0();
        }
        __syncthreads();

        // ---- S' = Qh·Kh + Ql·Kh + Qh·Kl  (q pre-scaled by 0.125·log2e) ----
        float s_acc[8][4] = {};
#pragma unroll
        for (int j = 0; j < 4; j++) {
#pragma unroll
            for (int s = 0; s < 4; s++) {
                uint32_t kad = bufb + A_KH +
                    (j * 16 + ((lane >> 4) & 1) * 8 + (lane & 7)) * (VP * 2) +
                    (s * 16 + ((lane >> 3) & 1) * 8) * 2;
                uint32_t khf[4], klf[4];
                ldsm4(khf, kad);
                ldsm4(klf, kad + (A_KL - A_KH));
                mma16816(s_acc[2 * j],     qhf[s], khf[0], khf[1]);
                mma16816(s_acc[2 * j],     qlf[s], khf[0], khf[1]);
                mma16816(s_acc[2 * j],     qhf[s], klf[0], klf[1]);
                mma16816(s_acc[2 * j + 1], qhf[s], khf[2], khf[3]);
                mma16816(s_acc[2 * j + 1], qlf[s], khf[2], khf[3]);
                mma16816(s_acc[2 * j + 1], qhf[s], klf[2], klf[3]);
            }
        }

        // ---- P = 2^(S'·mask - SHIFT2); accumulate row sums per-lane ----
        uint32_t pH[8], pH2[8], pL[8], pL2[8];
#pragma unroll
        for (int t8 = 0; t8 < 8; t8++) {
            uint32_t mw0 = *(uint32_t*)(sm + (bufb - sb) + A_MS + r0l * (VP * 2) + (t8 * 8 + q2) * 2);
            uint32_t mw1 = *(uint32_t*)(sm + (bufb - sb) + A_MS + (r0l + 8) * (VP * 2) + (t8 * 8 + q2) * 2);
            __nv_bfloat162 m0 = *(__nv_bfloat162*)&mw0;
            __nv_bfloat162 m1 = *(__nv_bfloat162*)&mw1;
            float p0 = fexp2(__fmaf_rn(s_acc[t8][0], __bfloat162float(m0.x), -SHIFT2_));
            float p1 = fexp2(__fmaf_rn(s_acc[t8][1], __bfloat162float(m0.y), -SHIFT2_));
            float p2 = fexp2(__fmaf_rn(s_acc[t8][2], __bfloat162float(m1.x), -SHIFT2_));
            float p3 = fexp2(__fmaf_rn(s_acc[t8][3], __bfloat162float(m1.y), -SHIFT2_));
            lsum0 += p0 + p1;
            lsum1 += p2 + p3;
            split_pack(p0, p1, pH[t8], pL[t8]);
            split_pack(p2, p3, pH2[t8], pL2[t8]);
        }

        // ---- O += Ph·Vh + Pl·Vh + Ph·Vl ----
#pragma unroll
        for (int nd = 0; nd < 4; nd++) {
#pragma unroll
            for (int kc = 0; kc < 4; kc++) {
                uint32_t vad = bufb + A_VH +
                    (kc * 16 + ((lane >> 3) & 1) * 8 + (lane & 7)) * (VP * 2) +
                    (nd * 16 + (lane >> 4) * 8) * 2;
                uint32_t vhf[4], vlf[4];
                ldsm4t(vhf, vad);
                ldsm4t(vlf, vad + (A_VL - A_VH));
                uint32_t ah[4]  = {pH[2 * kc], pH2[2 * kc], pH[2 * kc + 1], pH2[2 * kc + 1]};
                uint32_t alr[4] = {pL[2 * kc], pL2[2 * kc], pL[2 * kc + 1], pL2[2 * kc + 1]};
                mma16816(o_acc[2 * nd],     ah,  vhf[0], vhf[1]);
                mma16816(o_acc[2 * nd],     alr, vhf[0], vhf[1]);
                mma16816(o_acc[2 * nd],     ah,  vlf[0], vlf[1]);
                mma16816(o_acc[2 * nd + 1], ah,  vhf[2], vhf[3]);
                mma16816(o_acc[2 * nd + 1], alr, vhf[2], vhf[3]);
                mma16816(o_acc[2 * nd + 1], ah,  vlf[2], vlf[3]);
            }
        }
        __syncthreads();
    }

    lsum0 += __shfl_xor_sync(0xffffffffu, lsum0, 1);
    lsum0 += __shfl_xor_sync(0xffffffffu, lsum0, 2);
    lsum1 += __shfl_xor_sync(0xffffffffu, lsum1, 1);
    lsum1 += __shfl_xor_sync(0xffffffffu, lsum1, 2);

    float inv0 = 1.0f / lsum0, inv1 = 1.0f / lsum1;
    int n0 = row0 + r0l;
    size_t gr0 = ((size_t)b * N_ + n0) * C_;
    size_t gr1 = gr0 + (size_t)8 * C_;
#pragma unroll
    for (int t8 = 0; t8 < 8; t8++) {
        int col = h * D_ + t8 * 8 + q2;
        uint32_t hp, lp;
        split_pack(o_acc[t8][0] * inv0, o_acc[t8][1] * inv0, hp, lp);
        *(uint32_t*)(g_th + gr0 + col) = hp;
        *(uint32_t*)(g_tl + gr0 + col) = lp;
        split_pack(o_acc[t8][2] * inv1, o_acc[t8][3] * inv1, hp, lp);
        *(uint32_t*)(g_th + gr1 + col) = hp;
        *(uint32_t*)(g_tl + gr1 + col) = lp;
    }
}

// ---------------------------------------------------------------------------
extern "C" void kernel_launch(void* const* d_in, const int* in_sizes, int n_in,
                              void* d_out, int out_size) {
    const float* x      = (const float*)d_in[0];
    const float* w_qkv  = (const float*)d_in[1];
    const float* w_proj = (const float*)d_in[2];
    const float* b_proj = (const float*)d_in[3];
    const float* mask   = (const float*)d_in[4];
    float* out = (float*)d_out;
    (void)in_sizes; (void)n_in; (void)out_size;

    static __nv_bfloat16 *xh = nullptr, *xl, *wqh, *wql, *th, *tl, *wph, *wpl, *mb;
    static bool init_done = false;
    if (!init_done) {
        cudaFuncSetAttribute(attn_mma_kernel, cudaFuncAttributeMaxDynamicSharedMemorySize, ATT2_SMEM);
        cudaFuncSetAttribute(mm_mma_kernel, cudaFuncAttributeMaxDynamicSharedMemorySize, MM_SMEM);
        cudaGetSymbolAddress((void**)&xh,  g_xh);
        cudaGetSymbolAddress((void**)&xl,  g_xl);
        cudaGetSymbolAddress((void**)&wqh, g_wqh);
        cudaGetSymbolAddress((void**)&wql, g_wql);
        cudaGetSymbolAddress((void**)&th,  g_th);
        cudaGetSymbolAddress((void**)&tl,  g_tl);
        cudaGetSymbolAddress((void**)&wph, g_wph);
        cudaGetSymbolAddress((void**)&wpl, g_wpl);
        cudaGetSymbolAddress((void**)&mb,  g_maskb);
        init_done = true;
    }

    // Stage 0: fused fp32 -> hi/lo bf16 splits + mask conversion (one launch)
    preproc_kernel<<<QTOT / 256, 256>>>(x, w_qkv, w_proj, mask);

    // Stage 1: QKV projection (epilogue emits hi/lo bf16 q,k,v; q pre-scaled)
    mm_mma_kernel<<<dim3(3 * C_ / 128, (B_ * N_) / 128), 256, MM_SMEM>>>(
        xh, xl, wqh, wql, 0, nullptr, nullptr);

    // Stage 2: flash attention on tensor cores (writes g_th/g_tl directly)
    attn_mma_kernel<<<dim3(N_ / QT, B_ * H_), 256, ATT2_SMEM>>>(mb);

    // Stage 3: output projection + bias
    mm_mma_kernel<<<dim3(C_ / 128, (B_ * N_) / 128), 256, MM_SMEM>>>(
        th, tl, wph, wpl, 1, b_proj, out);
}

// round 11
// speedup vs baseline: 1.0374x; 1.0374x over previous
#include <cuda_runtime.h>
#include <cuda_bf16.h>
#include <math.h>
#include <stdint.h>

#define B_ 2
#define N_ 2048
#define C_ 1024
#define H_ 16
#define D_ 64
#define QSCALE_ (0.125f * 1.4426950408889634f)   // SCALE * log2(e), folded into q
#define SHIFT2_ 11.541560327111708f              // 8 * log2(e)

// ---------------------------------------------------------------------------
// Scratch (allocation-free): all operands as separate hi/lo bf16 arrays
// ---------------------------------------------------------------------------
__device__ __nv_bfloat16 g_qh[(size_t)B_ * H_ * N_ * D_];
__device__ __nv_bfloat16 g_ql[(size_t)B_ * H_ * N_ * D_];
__device__ __nv_bfloat16 g_kh[(size_t)B_ * H_ * N_ * D_];
__device__ __nv_bfloat16 g_kl[(size_t)B_ * H_ * N_ * D_];
__device__ __nv_bfloat16 g_vh[(size_t)B_ * H_ * N_ * D_];
__device__ __nv_bfloat16 g_vl[(size_t)B_ * H_ * N_ * D_];
__device__ __nv_bfloat16 g_maskb[(size_t)N_ * N_];

__device__ __nv_bfloat16 g_xh [(size_t)(B_ * N_) * C_];
__device__ __nv_bfloat16 g_xl [(size_t)(B_ * N_) * C_];
__device__ __nv_bfloat16 g_wqh[(size_t)(3 * C_) * C_];
__device__ __nv_bfloat16 g_wql[(size_t)(3 * C_) * C_];
__device__ __nv_bfloat16 g_th [(size_t)(B_ * N_) * C_];
__device__ __nv_bfloat16 g_tl [(size_t)(B_ * N_) * C_];
__device__ __nv_bfloat16 g_wph[(size_t)C_ * C_];
__device__ __nv_bfloat16 g_wpl[(size_t)C_ * C_];

// ---------------------------------------------------------------------------
// PTX helpers
// ---------------------------------------------------------------------------
__device__ __forceinline__ uint32_t smem_u32(const void* p) {
    uint32_t a;
    asm("{ .reg .u64 t; cvta.to.shared.u64 t, %1; cvt.u32.u64 %0, t; }" : "=r"(a) : "l"(p));
    return a;
}
__device__ __forceinline__ void cp16(uint32_t dst, const void* src) {
    asm volatile("cp.async.cg.shared.global [%0], [%1], 16;" :: "r"(dst), "l"(src));
}
__device__ __forceinline__ void cp_commit() {
    asm volatile("cp.async.commit_group;");
}
__device__ __forceinline__ void cp_wait0() {
    asm volatile("cp.async.wait_group 0;");
}
__device__ __forceinline__ void cp_wait1() {
    asm volatile("cp.async.wait_group 1;");
}
__device__ __forceinline__ void ldsm4(uint32_t* r, uint32_t a) {
    asm volatile("ldmatrix.sync.aligned.m8n8.x4.shared.b16 {%0,%1,%2,%3}, [%4];"
                 : "=r"(r[0]), "=r"(r[1]), "=r"(r[2]), "=r"(r[3]) : "r"(a));
}
__device__ __forceinline__ void ldsm4t(uint32_t* r, uint32_t a) {
    asm volatile("ldmatrix.sync.aligned.m8n8.x4.trans.shared.b16 {%0,%1,%2,%3}, [%4];"
                 : "=r"(r[0]), "=r"(r[1]), "=r"(r[2]), "=r"(r[3]) : "r"(a));
}
__device__ __forceinline__ void mma16816(float* c, const uint32_t* a, uint32_t b0, uint32_t b1) {
    asm volatile(
        "mma.sync.aligned.m16n8k16.row.col.f32.bf16.bf16.f32 "
        "{%0,%1,%2,%3}, {%4,%5,%6,%7}, {%8,%9}, {%0,%1,%2,%3};"
        : "+f"(c[0]), "+f"(c[1]), "+f"(c[2]), "+f"(c[3])
        : "r"(a[0]), "r"(a[1]), "r"(a[2]), "r"(a[3]), "r"(b0), "r"(b1));
}
__device__ __forceinline__ float fexp2(float x) {
    float r;
    asm("ex2.approx.f32 %0, %1;" : "=f"(r) : "f"(x));
    return r;
}
__device__ __forceinline__ void split_pack(float a, float b, uint32_t& hp, uint32_t& lp) {
    __nv_bfloat16 ha = __float2bfloat16(a), hb = __float2bfloat16(b);
    __nv_bfloat16 la = __float2bfloat16(a - __bfloat162float(ha));
    __nv_bfloat16 lb = __float2bfloat16(b - __bfloat162float(hb));
    __nv_bfloat162 hv = {ha, hb}, lv = {la, lb};
    hp = *(uint32_t*)&hv;
    lp = *(uint32_t*)&lv;
}

// ---------------------------------------------------------------------------
// Fused preprocessing: x/w_qkv/w_proj hi/lo splits + mask bf16 conversion.
// ---------------------------------------------------------------------------
#define QX  (B_ * N_ * C_ / 4)
#define QWQ (3 * C_ * C_ / 4)
#define QWP (C_ * C_ / 4)
#define QMK (N_ * N_ / 4)
#define QTOT (QX + QWQ + QWP + QMK)

__device__ __forceinline__ void split_quad(const float* __restrict__ src,
                                           __nv_bfloat16* __restrict__ dh,
                                           __nv_bfloat16* __restrict__ dl, int i4) {
    float4 a = ((const float4*)src)[i4];
    __nv_bfloat16 h0 = __float2bfloat16(a.x), h1 = __float2bfloat16(a.y);
    __nv_bfloat16 h2 = __float2bfloat16(a.z), h3 = __float2bfloat16(a.w);
    __nv_bfloat16 l0 = __float2bfloat16(a.x - __bfloat162float(h0));
    __nv_bfloat16 l1 = __float2bfloat16(a.y - __bfloat162float(h1));
    __nv_bfloat16 l2 = __float2bfloat16(a.z - __bfloat162float(h2));
    __nv_bfloat16 l3 = __float2bfloat16(a.w - __bfloat162float(h3));
    __nv_bfloat162 hA = {h0, h1}, hB = {h2, h3};
    __nv_bfloat162 lA = {l0, l1}, lB = {l2, l3};
    ((__nv_bfloat162*)dh)[2 * i4]     = hA;
    ((__nv_bfloat162*)dh)[2 * i4 + 1] = hB;
    ((__nv_bfloat162*)dl)[2 * i4]     = lA;
    ((__nv_bfloat162*)dl)[2 * i4 + 1] = lB;
}

__global__ __launch_bounds__(256) void preproc_kernel(const float* __restrict__ x,
                                                      const float* __restrict__ wqkv,
                                                      const float* __restrict__ wproj,
                                                      const float* __restrict__ mask) {
    int i = blockIdx.x * 256 + threadIdx.x;
    if (i < QX) {
        split_quad(x, g_xh, g_xl, i);
    } else if (i < QX + QWQ) {
        split_quad(wqkv, g_wqh, g_wql, i - QX);
    } else if (i < QX + QWQ + QWP) {
        split_quad(wproj, g_wph, g_wpl, i - QX - QWQ);
    } else {
        int j = i - QX - QWQ - QWP;
        float4 v = ((const float4*)mask)[j];
        __nv_bfloat162 p0 = {__float2bfloat16(v.x), __float2bfloat16(v.y)};
        __nv_bfloat162 p1 = {__float2bfloat16(v.z), __float2bfloat16(v.w)};
        ((__nv_bfloat162*)g_maskb)[2 * j]     = p0;
        ((__nv_bfloat162*)g_maskb)[2 * j + 1] = p1;
    }
}

// ---------------------------------------------------------------------------
// mma.sync GEMM, CTA 128x128, warp 64x32, BK=32 double-buffered (R8 skeleton),
// with TERM-MAJOR MMA ordering over i-pairs (8 distinct accumulators between
// reuses) to break accumulator RAW chains.
// ---------------------------------------------------------------------------
#define PITCH 40
#define GK 1024
#define MITERS (GK / 32)         // 32
#define T_AH 0
#define T_AL (128 * PITCH)
#define T_BH (2 * 128 * PITCH)
#define T_BL (3 * 128 * PITCH)
#define MMBUF (4 * 128 * PITCH)              // 20480 elems = 40960 B
#define MM_SMEM (2 * MMBUF * 2)              // 81920 B

__global__ __launch_bounds__(256, 2) void mm_mma_kernel(const __nv_bfloat16* __restrict__ Ah,
                                                        const __nv_bfloat16* __restrict__ Al,
                                                        const __nv_bfloat16* __restrict__ Bh,
                                                        const __nv_bfloat16* __restrict__ Bl,
                                                        int mode,
                                                        const float* __restrict__ bias,
                                                        float* __restrict__ outp) {
    extern __shared__ __nv_bfloat16 smb[];

    const int tid = threadIdx.x;
    const int wid = tid >> 5;
    const int lane = tid & 31;
    const int brow = blockIdx.y * 128;
    const int bcol = blockIdx.x * 128;
    const int mbase = (wid >> 2) * 64;
    const int nbase = (wid & 3) * 32;

    const uint32_t sbase = smem_u32(smb);

    const int lr0 = tid >> 1;
    const int lq0 = (tid & 1) * 2;

    auto load_tile = [&](int kt, int buf) {
        const int k0 = kt * 32;
        const size_t go = (size_t)(brow + lr0) * GK + k0;
        const size_t gob = (size_t)(bcol + lr0) * GK + k0;
        uint32_t sb = sbase + buf * (MMBUF * 2) + (lr0 * PITCH) * 2;
#pragma unroll
        for (int q = 0; q < 2; q++) {
            cp16(sb + T_AH * 2 + (lq0 + q) * 16, Ah + go  + (lq0 + q) * 8);
            cp16(sb + T_AL * 2 + (lq0 + q) * 16, Al + go  + (lq0 + q) * 8);
            cp16(sb + T_BH * 2 + (lq0 + q) * 16, Bh + gob + (lq0 + q) * 8);
            cp16(sb + T_BL * 2 + (lq0 + q) * 16, Bl + gob + (lq0 + q) * 8);
        }
        cp_commit();
    };

    float acc[4][4][4] = {};

    load_tile(0, 0);
    cp_wait0();
    __syncthreads();

    for (int kt = 0; kt < MITERS; kt++) {
        const int buf = kt & 1;
        const uint32_t sb = sbase + buf * (MMBUF * 2);
        if (kt + 1 < MITERS) load_tile(kt + 1, buf ^ 1);

#pragma unroll
        for (int s = 0; s < 2; s++) {
            uint32_t bh[2][4], bl[2][4];
#pragma unroll
            for (int j = 0; j < 2; j++) {
                int row = nbase + j * 16 + ((lane >> 4) & 1) * 8 + (lane & 7);
                int col = s * 16 + ((lane >> 3) & 1) * 8;
                uint32_t ba = sb + (row * PITCH + col) * 2;
                ldsm4(bh[j], ba + T_BH * 2);
                ldsm4(bl[j], ba + T_BL * 2);
            }
            // process i in pairs; term-major over 8 distinct accumulators
#pragma unroll
            for (int ip = 0; ip < 2; ip++) {
                uint32_t ah[2][4], al[2][4];
#pragma unroll
                for (int ii = 0; ii < 2; ii++) {
                    int i = 2 * ip + ii;
                    uint32_t aa = sb +
                        ((mbase + i * 16 + (lane & 15)) * PITCH + s * 16 + (lane >> 4) * 8) * 2;
                    ldsm4(ah[ii], aa + T_AH * 2);
                    ldsm4(al[ii], aa + T_AL * 2);
                }
                // term 1: Ah·Bh (8 MMAs, 8 distinct accs)
#pragma unroll
                for (int ii = 0; ii < 2; ii++)
#pragma unroll
                    for (int j = 0; j < 2; j++) {
                        mma16816(acc[2 * ip + ii][2 * j],     ah[ii], bh[j][0], bh[j][1]);
                        mma16816(acc[2 * ip + ii][2 * j + 1], ah[ii], bh[j][2], bh[j][3]);
                    }
                // term 2: Al·Bh
#pragma unroll
                for (int ii = 0; ii < 2; ii++)
#pragma unroll
                    for (int j = 0; j < 2; j++) {
                        mma16816(acc[2 * ip + ii][2 * j],     al[ii], bh[j][0], bh[j][1]);
                        mma16816(acc[2 * ip + ii][2 * j + 1], al[ii], bh[j][2], bh[j][3]);
                    }
                // term 3: Ah·Bl
#pragma unroll
                for (int ii = 0; ii < 2; ii++)
#pragma unroll
                    for (int j = 0; j < 2; j++) {
                        mma16816(acc[2 * ip + ii][2 * j],     ah[ii], bl[j][0], bl[j][1]);
                        mma16816(acc[2 * ip + ii][2 * j + 1], ah[ii], bl[j][2], bl[j][3]);
                    }
            }
        }

        if (kt + 1 < MITERS) cp_wait0();
        __syncthreads();
    }

    const int r0 = brow + mbase + (lane >> 2);
    const int cq = (lane & 3) * 2;
#pragma unroll
    for (int i = 0; i < 4; i++) {
#pragma unroll
        for (int jj = 0; jj < 4; jj++) {
            const float* c = acc[i][jj];
            int gc = bcol + nbase + jj * 8 + cq;
#pragma unroll
            for (int hrow = 0; hrow < 2; hrow++) {
                int gi = r0 + i * 16 + hrow * 8;
                float vx = c[hrow * 2 + 0], vy = c[hrow * 2 + 1];
                if (mode == 0) {
                    int bb = gi >> 11;
                    int nseq = gi & (N_ - 1);
                    int three = gc >> 10;
                    int h = (gc >> 6) & (H_ - 1);
                    int d = gc & (D_ - 1);
                    if (three == 0) { vx *= QSCALE_; vy *= QSCALE_; }
                    uint32_t hp, lp;
                    split_pack(vx, vy, hp, lp);
                    __nv_bfloat16 *hd, *ld;
                    if (three == 0)      { hd = g_qh; ld = g_ql; }
                    else if (three == 1) { hd = g_kh; ld = g_kl; }
                    else                 { hd = g_vh; ld = g_vl; }
                    size_t off = (((size_t)bb * H_ + h) * N_ + nseq) * D_ + d;
                    *(uint32_t*)(hd + off) = hp;
                    *(uint32_t*)(ld + off) = lp;
                } else {
                    float2 val = {vx + bias[gc], vy + bias[gc + 1]};
                    *(float2*)&outp[(size_t)gi * C_ + gc] = val;
                }
            }
        }
    }
}

// ---------------------------------------------------------------------------
// Flash attention: fixed-shift base-2 softmax, 3-term splits, TERM-MAJOR MMA
// ordering (S: K-frags for all j held per s-step; PV: kc outer, V-frags for
// all nd held) to break accumulator RAW chains.
// ---------------------------------------------------------------------------
#define QT 128
#define KT 64
#define VP 72
#define A_QH 0
#define A_QL (QT * VP * 2)
#define A_BUF (2 * QT * VP * 2)
#define A_KH 0
#define A_KL (KT * VP * 2)
#define A_VH (2 * KT * VP * 2)
#define A_VL (3 * KT * VP * 2)
#define A_MS (4 * KT * VP * 2)
#define A_BUFSZ (4 * KT * VP * 2 + QT * VP * 2)
#define ATT2_SMEM (A_BUF + 2 * A_BUFSZ)           // 147456

__global__ __launch_bounds__(256) void attn_mma_kernel(const __nv_bfloat16* __restrict__ maskb) {
    extern __shared__ char sm[];
    const uint32_t sb = smem_u32(sm);
    const int tid = threadIdx.x, wid = tid >> 5, lane = tid & 31;
    const int bh = blockIdx.y;
    const int row0 = blockIdx.x * QT;
    const int b = bh >> 4, h = bh & (H_ - 1);
    const size_t hoff = (size_t)bh * N_ * D_;
    const __nv_bfloat16 *qhp = g_qh + hoff, *qlp = g_ql + hoff;
    const __nv_bfloat16 *khp = g_kh + hoff, *klp = g_kl + hoff;
    const __nv_bfloat16 *vhp = g_vh + hoff, *vlp = g_vl + hoff;

    for (int idx = tid; idx < QT * 8; idx += 256) {
        int r = idx >> 3, cc = idx & 7;
        *(uint4*)(sm + A_QH + r * (VP * 2) + cc * 16) =
            *(const uint4*)(qhp + (size_t)(row0 + r) * D_ + cc * 8);
        *(uint4*)(sm + A_QL + r * (VP * 2) + cc * 16) =
            *(const uint4*)(qlp + (size_t)(row0 + r) * D_ + cc * 8);
    }
    __syncthreads();

    const int mrow0 = wid * 16;
    uint32_t qhf[4][4], qlf[4][4];
#pragma unroll
    for (int s = 0; s < 4; s++) {
        uint32_t ad = sb + A_QH + (mrow0 + (lane & 15)) * (VP * 2) + (s * 16 + (lane >> 4) * 8) * 2;
        ldsm4(qhf[s], ad);
        ldsm4(qlf[s], ad + (A_QL - A_QH));
    }

    auto prefetch = [&](int t, uint32_t bufb) {
        const int k0 = t * KT;
#pragma unroll
        for (int i = 0; i < 2; i++) {
            int idx = tid + i * 256;
            int r = idx >> 3, cc = idx & 7;
            uint32_t ro = r * (VP * 2) + cc * 16;
            size_t go = (size_t)(k0 + r) * D_ + cc * 8;
            cp16(bufb + A_KH + ro, khp + go);
            cp16(bufb + A_KL + ro, klp + go);
            cp16(bufb + A_VH + ro, vhp + go);
            cp16(bufb + A_VL + ro, vlp + go);
        }
#pragma unroll
        for (int i = 0; i < 4; i++) {
            int idx = tid + i * 256;
            int r = idx >> 3, cc = idx & 7;
            cp16(bufb + A_MS + r * (VP * 2) + cc * 16,
                 maskb + (size_t)(row0 + r) * N_ + k0 + cc * 8);
        }
        cp_commit();
    };

    float o_acc[8][4] = {};
    float lsum0 = 0.f, lsum1 = 0.f;
    const int q2 = (lane & 3) * 2;
    const int r0l = mrow0 + (lane >> 2);

    prefetch(0, sb + A_BUF);

    for (int t = 0; t < N_ / KT; t++) {
        const uint32_t bufb = sb + A_BUF + (t & 1) * A_BUFSZ;
        if (t + 1 < N_ / KT) {
            prefetch(t + 1, sb + A_BUF + ((t + 1) & 1) * A_BUFSZ);
            cp_wait1();
        } else {
            cp_wait0();
        }
        __syncthreads();

        // ---- S' = Qh·Kh + Ql·Kh + Qh·Kl, term-major over 8 accumulators ----
        float s_acc[8][4] = {};
#pragma unroll
        for (int s = 0; s < 4; s++) {
            uint32_t khf[4][4], klf[4][4];
#pragma unroll
            for (int j = 0; j < 4; j++) {
                uint32_t kad = bufb + A_KH +
                    (j * 16 + ((lane >> 4) & 1) * 8 + (lane & 7)) * (VP * 2) +
                    (s * 16 + ((lane >> 3) & 1) * 8) * 2;
                ldsm4(khf[j], kad);
                ldsm4(klf[j], kad + (A_KL - A_KH));
            }
            // hh: 8 distinct accs
#pragma unroll
            for (int j = 0; j < 4; j++) {
                mma16816(s_acc[2 * j],     qhf[s], khf[j][0], khf[j][1]);
                mma16816(s_acc[2 * j + 1], qhf[s], khf[j][2], khf[j][3]);
            }
            // lh
#pragma unroll
            for (int j = 0; j < 4; j++) {
                mma16816(s_acc[2 * j],     qlf[s], khf[j][0], khf[j][1]);
                mma16816(s_acc[2 * j + 1], qlf[s], khf[j][2], khf[j][3]);
            }
            // hl
#pragma unroll
            for (int j = 0; j < 4; j++) {
                mma16816(s_acc[2 * j],     qhf[s], klf[j][0], klf[j][1]);
                mma16816(s_acc[2 * j + 1], qhf[s], klf[j][2], klf[j][3]);
            }
        }

        // ---- P = 2^(S'·mask - SHIFT2); accumulate row sums per-lane ----
        uint32_t pH[8], pH2[8], pL[8], pL2[8];
#pragma unroll
        for (int t8 = 0; t8 < 8; t8++) {
            uint32_t mw0 = *(uint32_t*)(sm + (bufb - sb) + A_MS + r0l * (VP * 2) + (t8 * 8 + q2) * 2);
            uint32_t mw1 = *(uint32_t*)(sm + (bufb - sb) + A_MS + (r0l + 8) * (VP * 2) + (t8 * 8 + q2) * 2);
            __nv_bfloat162 m0 = *(__nv_bfloat162*)&mw0;
            __nv_bfloat162 m1 = *(__nv_bfloat162*)&mw1;
            float p0 = fexp2(__fmaf_rn(s_acc[t8][0], __bfloat162float(m0.x), -SHIFT2_));
            float p1 = fexp2(__fmaf_rn(s_acc[t8][1], __bfloat162float(m0.y), -SHIFT2_));
            float p2 = fexp2(__fmaf_rn(s_acc[t8][2], __bfloat162float(m1.x), -SHIFT2_));
            float p3 = fexp2(__fmaf_rn(s_acc[t8][3], __bfloat162float(m1.y), -SHIFT2_));
            lsum0 += p0 + p1;
            lsum1 += p2 + p3;
            split_pack(p0, p1, pH[t8], pL[t8]);
            split_pack(p2, p3, pH2[t8], pL2[t8]);
        }

        // ---- O += Ph·Vh + Pl·Vh + Ph·Vl, kc outer, term-major over 8 accs ----
#pragma unroll
        for (int kc = 0; kc < 4; kc++) {
            uint32_t vhf[4][4], vlf[4][4];
#pragma unroll
            for (int nd = 0; nd < 4; nd++) {
                uint32_t vad = bufb + A_VH +
                    (kc * 16 + ((lane >> 3) & 1) * 8 + (lane & 7)) * (VP * 2) +
                    (nd * 16 + (lane >> 4) * 8) * 2;
                ldsm4t(vhf[nd], vad);
                ldsm4t(vlf[nd], vad + (A_VL - A_VH));
            }
            uint32_t ah[4]  = {pH[2 * kc], pH2[2 * kc], pH[2 * kc + 1], pH2[2 * kc + 1]};
            uint32_t alr[4] = {pL[2 * kc], pL2[2 * kc], pL[2 * kc + 1], pL2[2 * kc + 1]};
            // hh: 8 distinct accs
#pragma unroll
            for (int nd = 0; nd < 4; nd++) {
                mma16816(o_acc[2 * nd],     ah, vhf[nd][0], vhf[nd][1]);
                mma16816(o_acc[2 * nd + 1], ah, vhf[nd][2], vhf[nd][3]);
            }
            // lh
#pragma unroll
            for (int nd = 0; nd < 4; nd++) {
                mma16816(o_acc[2 * nd],     alr, vhf[nd][0], vhf[nd][1]);
                mma16816(o_acc[2 * nd + 1], alr, vhf[nd][2], vhf[nd][3]);
            }
            // hl
#pragma unroll
            for (int nd = 0; nd < 4; nd++) {
                mma16816(o_acc[2 * nd],     ah, vlf[nd][0], vlf[nd][1]);
                mma16816(o_acc[2 * nd + 1], ah, vlf[nd][2], vlf[nd][3]);
            }
        }
        __syncthreads();
    }

    lsum0 += __shfl_xor_sync(0xffffffffu, lsum0, 1);
    lsum0 += __shfl_xor_sync(0xffffffffu, lsum0, 2);
    lsum1 += __shfl_xor_sync(0xffffffffu, lsum1, 1);
    lsum1 += __shfl_xor_sync(0xffffffffu, lsum1, 2);

    float inv0 = 1.0f / lsum0, inv1 = 1.0f / lsum1;
    int n0 = row0 + r0l;
    size_t gr0 = ((size_t)b * N_ + n0) * C_;
    size_t gr1 = gr0 + (size_t)8 * C_;
#pragma unroll
    for (int t8 = 0; t8 < 8; t8++) {
        int col = h * D_ + t8 * 8 + q2;
        uint32_t hp, lp;
        split_pack(o_acc[t8][0] * inv0, o_acc[t8][1] * inv0, hp, lp);
        *(uint32_t*)(g_th + gr0 + col) = hp;
        *(uint32_t*)(g_tl + gr0 + col) = lp;
        split_pack(o_acc[t8][2] * inv1, o_acc[t8][3] * inv1, hp, lp);
        *(uint32_t*)(g_th + gr1 + col) = hp;
        *(uint32_t*)(g_tl + gr1 + col) = lp;
    }
}

// ---------------------------------------------------------------------------
extern "C" void kernel_launch(void* const* d_in, const int* in_sizes, int n_in,
                              void* d_out, int out_size) {
    const float* x      = (const float*)d_in[0];
    const float* w_qkv  = (const float*)d_in[1];
    const float* w_proj = (const float*)d_in[2];
    const float* b_proj = (const float*)d_in[3];
    const float* mask   = (const float*)d_in[4];
    float* out = (float*)d_out;
    (void)in_sizes; (void)n_in; (void)out_size;

    static __nv_bfloat16 *xh = nullptr, *xl, *wqh, *wql, *th, *tl, *wph, *wpl, *mb;
    static bool init_done = false;
    if (!init_done) {
        cudaFuncSetAttribute(attn_mma_kernel, cudaFuncAttributeMaxDynamicSharedMemorySize, ATT2_SMEM);
        cudaFuncSetAttribute(mm_mma_kernel, cudaFuncAttributeMaxDynamicSharedMemorySize, MM_SMEM);
        cudaGetSymbolAddress((void**)&xh,  g_xh);
        cudaGetSymbolAddress((void**)&xl,  g_xl);
        cudaGetSymbolAddress((void**)&wqh, g_wqh);
        cudaGetSymbolAddress((void**)&wql, g_wql);
        cudaGetSymbolAddress((void**)&th,  g_th);
        cudaGetSymbolAddress((void**)&tl,  g_tl);
        cudaGetSymbolAddress((void**)&wph, g_wph);
        cudaGetSymbolAddress((void**)&wpl, g_wpl);
        cudaGetSymbolAddress((void**)&mb,  g_maskb);
        init_done = true;
    }

    // Stage 0: fused fp32 -> hi/lo bf16 splits + mask conversion (one launch)
    preproc_kernel<<<QTOT / 256, 256>>>(x, w_qkv, w_proj, mask);

    // Stage 1: QKV projection (epilogue emits hi/lo bf16 q,k,v; q pre-scaled)
    mm_mma_kernel<<<dim3(3 * C_ / 128, (B_ * N_) / 128), 256, MM_SMEM>>>(
        xh, xl, wqh, wql, 0, nullptr, nullptr);

    // Stage 2: flash attention on tensor cores (writes g_th/g_tl directly)
    attn_mma_kernel<<<dim3(N_ / QT, B_ * H_), 256, ATT2_SMEM>>>(mb);

    // Stage 3: output projection + bias
    mm_mma_kernel<<<dim3(C_ / 128, (B_ * N_) / 128), 256, MM_SMEM>>>(
        th, tl, wph, wpl, 1, b_proj, out);
}

// round 12
// speedup vs baseline: 1.1073x; 1.0675x over previous
#include <cuda_runtime.h>
#include <cuda_bf16.h>
#include <math.h>
#include <stdint.h>

#define B_ 2
#define N_ 2048
#define C_ 1024
#define H_ 16
#define D_ 64
#define QSCALE_ (0.125f * 1.4426950408889634f)   // SCALE * log2(e), folded into q
#define SHIFT2_ 11.541560327111708f              // 8 * log2(e)

// ---------------------------------------------------------------------------
// Scratch (allocation-free): all operands as separate hi/lo bf16 arrays
// ---------------------------------------------------------------------------
__device__ __nv_bfloat16 g_qh[(size_t)B_ * H_ * N_ * D_];
__device__ __nv_bfloat16 g_ql[(size_t)B_ * H_ * N_ * D_];
__device__ __nv_bfloat16 g_kh[(size_t)B_ * H_ * N_ * D_];
__device__ __nv_bfloat16 g_kl[(size_t)B_ * H_ * N_ * D_];
__device__ __nv_bfloat16 g_vh[(size_t)B_ * H_ * N_ * D_];
__device__ __nv_bfloat16 g_vl[(size_t)B_ * H_ * N_ * D_];
__device__ __nv_bfloat16 g_maskb[(size_t)N_ * N_];

__device__ __nv_bfloat16 g_xh [(size_t)(B_ * N_) * C_];
__device__ __nv_bfloat16 g_xl [(size_t)(B_ * N_) * C_];
__device__ __nv_bfloat16 g_wqh[(size_t)(3 * C_) * C_];
__device__ __nv_bfloat16 g_wql[(size_t)(3 * C_) * C_];
__device__ __nv_bfloat16 g_th [(size_t)(B_ * N_) * C_];
__device__ __nv_bfloat16 g_tl [(size_t)(B_ * N_) * C_];
__device__ __nv_bfloat16 g_wph[(size_t)C_ * C_];
__device__ __nv_bfloat16 g_wpl[(size_t)C_ * C_];

// ---------------------------------------------------------------------------
// PTX helpers
// ---------------------------------------------------------------------------
__device__ __forceinline__ uint32_t smem_u32(const void* p) {
    uint32_t a;
    asm("{ .reg .u64 t; cvta.to.shared.u64 t, %1; cvt.u32.u64 %0, t; }" : "=r"(a) : "l"(p));
    return a;
}
__device__ __forceinline__ void cp16(uint32_t dst, const void* src) {
    asm volatile("cp.async.cg.shared.global [%0], [%1], 16;" :: "r"(dst), "l"(src));
}
__device__ __forceinline__ void cp_commit() {
    asm volatile("cp.async.commit_group;");
}
__device__ __forceinline__ void cp_wait0() {
    asm volatile("cp.async.wait_group 0;");
}
__device__ __forceinline__ void cp_wait1() {
    asm volatile("cp.async.wait_group 1;");
}
__device__ __forceinline__ void ldsm4(uint32_t* r, uint32_t a) {
    asm volatile("ldmatrix.sync.aligned.m8n8.x4.shared.b16 {%0,%1,%2,%3}, [%4];"
                 : "=r"(r[0]), "=r"(r[1]), "=r"(r[2]), "=r"(r[3]) : "r"(a));
}
__device__ __forceinline__ void ldsm4t(uint32_t* r, uint32_t a) {
    asm volatile("ldmatrix.sync.aligned.m8n8.x4.trans.shared.b16 {%0,%1,%2,%3}, [%4];"
                 : "=r"(r[0]), "=r"(r[1]), "=r"(r[2]), "=r"(r[3]) : "r"(a));
}
__device__ __forceinline__ void mma16816(float* c, const uint32_t* a, uint32_t b0, uint32_t b1) {
    asm volatile(
        "mma.sync.aligned.m16n8k16.row.col.f32.bf16.bf16.f32 "
        "{%0,%1,%2,%3}, {%4,%5,%6,%7}, {%8,%9}, {%0,%1,%2,%3};"
        : "+f"(c[0]), "+f"(c[1]), "+f"(c[2]), "+f"(c[3])
        : "r"(a[0]), "r"(a[1]), "r"(a[2]), "r"(a[3]), "r"(b0), "r"(b1));
}
__device__ __forceinline__ float fexp2(float x) {
    float r;
    asm("ex2.approx.f32 %0, %1;" : "=f"(r) : "f"(x));
    return r;
}
__device__ __forceinline__ void split_pack(float a, float b, uint32_t& hp, uint32_t& lp) {
    __nv_bfloat16 ha = __float2bfloat16(a), hb = __float2bfloat16(b);
    __nv_bfloat16 la = __float2bfloat16(a - __bfloat162float(ha));
    __nv_bfloat16 lb = __float2bfloat16(b - __bfloat162float(hb));
    __nv_bfloat162 hv = {ha, hb}, lv = {la, lb};
    hp = *(uint32_t*)&hv;
    lp = *(uint32_t*)&lv;
}

// ---------------------------------------------------------------------------
// Fused preprocessing: x/w_qkv/w_proj hi/lo splits + mask bf16 conversion.
// ---------------------------------------------------------------------------
#define QX  (B_ * N_ * C_ / 4)
#define QWQ (3 * C_ * C_ / 4)
#define QWP (C_ * C_ / 4)
#define QMK (N_ * N_ / 4)
#define QTOT (QX + QWQ + QWP + QMK)

__device__ __forceinline__ void split_quad(const float* __restrict__ src,
                                           __nv_bfloat16* __restrict__ dh,
                                           __nv_bfloat16* __restrict__ dl, int i4) {
    float4 a = ((const float4*)src)[i4];
    __nv_bfloat16 h0 = __float2bfloat16(a.x), h1 = __float2bfloat16(a.y);
    __nv_bfloat16 h2 = __float2bfloat16(a.z), h3 = __float2bfloat16(a.w);
    __nv_bfloat16 l0 = __float2bfloat16(a.x - __bfloat162float(h0));
    __nv_bfloat16 l1 = __float2bfloat16(a.y - __bfloat162float(h1));
    __nv_bfloat16 l2 = __float2bfloat16(a.z - __bfloat162float(h2));
    __nv_bfloat16 l3 = __float2bfloat16(a.w - __bfloat162float(h3));
    __nv_bfloat162 hA = {h0, h1}, hB = {h2, h3};
    __nv_bfloat162 lA = {l0, l1}, lB = {l2, l3};
    ((__nv_bfloat162*)dh)[2 * i4]     = hA;
    ((__nv_bfloat162*)dh)[2 * i4 + 1] = hB;
    ((__nv_bfloat162*)dl)[2 * i4]     = lA;
    ((__nv_bfloat162*)dl)[2 * i4 + 1] = lB;
}

__global__ __launch_bounds__(256) void preproc_kernel(const float* __restrict__ x,
                                                      const float* __restrict__ wqkv,
                                                      const float* __restrict__ wproj,
                                                      const float* __restrict__ mask) {
    int i = blockIdx.x * 256 + threadIdx.x;
    if (i < QX) {
        split_quad(x, g_xh, g_xl, i);
    } else if (i < QX + QWQ) {
        split_quad(wqkv, g_wqh, g_wql, i - QX);
    } else if (i < QX + QWQ + QWP) {
        split_quad(wproj, g_wph, g_wpl, i - QX - QWQ);
    } else {
        int j = i - QX - QWQ - QWP;
        float4 v = ((const float4*)mask)[j];
        __nv_bfloat162 p0 = {__float2bfloat16(v.x), __float2bfloat16(v.y)};
        __nv_bfloat162 p1 = {__float2bfloat16(v.z), __float2bfloat16(v.w)};
        ((__nv_bfloat162*)g_maskb)[2 * j]     = p0;
        ((__nv_bfloat162*)g_maskb)[2 * j + 1] = p1;
    }
}

// ---------------------------------------------------------------------------
// mma.sync GEMM (R11, unchanged — protected win): CTA 128x128, warp 64x32,
// BK=32 double-buffered, term-major MMA ordering over i-pairs.
// ---------------------------------------------------------------------------
#define PITCH 40
#define GK 1024
#define MITERS (GK / 32)         // 32
#define T_AH 0
#define T_AL (128 * PITCH)
#define T_BH (2 * 128 * PITCH)
#define T_BL (3 * 128 * PITCH)
#define MMBUF (4 * 128 * PITCH)              // 20480 elems = 40960 B
#define MM_SMEM (2 * MMBUF * 2)              // 81920 B

__global__ __launch_bounds__(256, 2) void mm_mma_kernel(const __nv_bfloat16* __restrict__ Ah,
                                                        const __nv_bfloat16* __restrict__ Al,
                                                        const __nv_bfloat16* __restrict__ Bh,
                                                        const __nv_bfloat16* __restrict__ Bl,
                                                        int mode,
                                                        const float* __restrict__ bias,
                                                        float* __restrict__ outp) {
    extern __shared__ __nv_bfloat16 smb[];

    const int tid = threadIdx.x;
    const int wid = tid >> 5;
    const int lane = tid & 31;
    const int brow = blockIdx.y * 128;
    const int bcol = blockIdx.x * 128;
    const int mbase = (wid >> 2) * 64;
    const int nbase = (wid & 3) * 32;

    const uint32_t sbase = smem_u32(smb);

    const int lr0 = tid >> 1;
    const int lq0 = (tid & 1) * 2;

    auto load_tile = [&](int kt, int buf) {
        const int k0 = kt * 32;
        const size_t go = (size_t)(brow + lr0) * GK + k0;
        const size_t gob = (size_t)(bcol + lr0) * GK + k0;
        uint32_t sb = sbase + buf * (MMBUF * 2) + (lr0 * PITCH) * 2;
#pragma unroll
        for (int q = 0; q < 2; q++) {
            cp16(sb + T_AH * 2 + (lq0 + q) * 16, Ah + go  + (lq0 + q) * 8);
            cp16(sb + T_AL * 2 + (lq0 + q) * 16, Al + go  + (lq0 + q) * 8);
            cp16(sb + T_BH * 2 + (lq0 + q) * 16, Bh + gob + (lq0 + q) * 8);
            cp16(sb + T_BL * 2 + (lq0 + q) * 16, Bl + gob + (lq0 + q) * 8);
        }
        cp_commit();
    };

    float acc[4][4][4] = {};

    load_tile(0, 0);
    cp_wait0();
    __syncthreads();

    for (int kt = 0; kt < MITERS; kt++) {
        const int buf = kt & 1;
        const uint32_t sb = sbase + buf * (MMBUF * 2);
        if (kt + 1 < MITERS) load_tile(kt + 1, buf ^ 1);

#pragma unroll
        for (int s = 0; s < 2; s++) {
            uint32_t bh[2][4], bl[2][4];
#pragma unroll
            for (int j = 0; j < 2; j++) {
                int row = nbase + j * 16 + ((lane >> 4) & 1) * 8 + (lane & 7);
                int col = s * 16 + ((lane >> 3) & 1) * 8;
                uint32_t ba = sb + (row * PITCH + col) * 2;
                ldsm4(bh[j], ba + T_BH * 2);
                ldsm4(bl[j], ba + T_BL * 2);
            }
#pragma unroll
            for (int ip = 0; ip < 2; ip++) {
                uint32_t ah[2][4], al[2][4];
#pragma unroll
                for (int ii = 0; ii < 2; ii++) {
                    int i = 2 * ip + ii;
                    uint32_t aa = sb +
                        ((mbase + i * 16 + (lane & 15)) * PITCH + s * 16 + (lane >> 4) * 8) * 2;
                    ldsm4(ah[ii], aa + T_AH * 2);
                    ldsm4(al[ii], aa + T_AL * 2);
                }
#pragma unroll
                for (int ii = 0; ii < 2; ii++)
#pragma unroll
                    for (int j = 0; j < 2; j++) {
                        mma16816(acc[2 * ip + ii][2 * j],     ah[ii], bh[j][0], bh[j][1]);
                        mma16816(acc[2 * ip + ii][2 * j + 1], ah[ii], bh[j][2], bh[j][3]);
                    }
#pragma unroll
                for (int ii = 0; ii < 2; ii++)
#pragma unroll
                    for (int j = 0; j < 2; j++) {
                        mma16816(acc[2 * ip + ii][2 * j],     al[ii], bh[j][0], bh[j][1]);
                        mma16816(acc[2 * ip + ii][2 * j + 1], al[ii], bh[j][2], bh[j][3]);
                    }
#pragma unroll
                for (int ii = 0; ii < 2; ii++)
#pragma unroll
                    for (int j = 0; j < 2; j++) {
                        mma16816(acc[2 * ip + ii][2 * j],     ah[ii], bl[j][0], bl[j][1]);
                        mma16816(acc[2 * ip + ii][2 * j + 1], ah[ii], bl[j][2], bl[j][3]);
                    }
            }
        }

        if (kt + 1 < MITERS) cp_wait0();
        __syncthreads();
    }

    const int r0 = brow + mbase + (lane >> 2);
    const int cq = (lane & 3) * 2;
#pragma unroll
    for (int i = 0; i < 4; i++) {
#pragma unroll
        for (int jj = 0; jj < 4; jj++) {
            const float* c = acc[i][jj];
            int gc = bcol + nbase + jj * 8 + cq;
#pragma unroll
            for (int hrow = 0; hrow < 2; hrow++) {
                int gi = r0 + i * 16 + hrow * 8;
                float vx = c[hrow * 2 + 0], vy = c[hrow * 2 + 1];
                if (mode == 0) {
                    int bb = gi >> 11;
                    int nseq = gi & (N_ - 1);
                    int three = gc >> 10;
                    int h = (gc >> 6) & (H_ - 1);
                    int d = gc & (D_ - 1);
                    if (three == 0) { vx *= QSCALE_; vy *= QSCALE_; }
                    uint32_t hp, lp;
                    split_pack(vx, vy, hp, lp);
                    __nv_bfloat16 *hd, *ld;
                    if (three == 0)      { hd = g_qh; ld = g_ql; }
                    else if (three == 1) { hd = g_kh; ld = g_kl; }
                    else                 { hd = g_vh; ld = g_vl; }
                    size_t off = (((size_t)bb * H_ + h) * N_ + nseq) * D_ + d;
                    *(uint32_t*)(hd + off) = hp;
                    *(uint32_t*)(ld + off) = lp;
                } else {
                    float2 val = {vx + bias[gc], vy + bias[gc + 1]};
                    *(float2*)&outp[(size_t)gi * C_ + gc] = val;
                }
            }
        }
    }
}

// ---------------------------------------------------------------------------
// Flash attention, KT=32 tiles -> 94KB smem -> 2 CTAs/SM (16 warps/SM).
// Fixed-shift base-2 softmax, 3-term splits, term-major MMA ordering.
// ---------------------------------------------------------------------------
#define QT 128
#define KT 32
#define VP 72                    // K/V row pitch (bf16): 64 d + pad
#define MP 40                    // mask row pitch (bf16): 32 cols + pad
#define A_QH 0
#define A_QL (QT * VP * 2)                        // 18432
#define A_BUF (2 * QT * VP * 2)                   // 36864
#define A_KH 0
#define A_KL (KT * VP * 2)                        // 4608
#define A_VH (2 * KT * VP * 2)                    // 9216
#define A_VL (3 * KT * VP * 2)                    // 13824
#define A_MS (4 * KT * VP * 2)                    // 18432
#define A_BUFSZ (4 * KT * VP * 2 + QT * MP * 2)   // 28672
#define ATT2_SMEM (A_BUF + 2 * A_BUFSZ)           // 94208 -> 2 CTAs/SM

__global__ __launch_bounds__(256, 2) void attn_mma_kernel(const __nv_bfloat16* __restrict__ maskb) {
    extern __shared__ char sm[];
    const uint32_t sb = smem_u32(sm);
    const int tid = threadIdx.x, wid = tid >> 5, lane = tid & 31;
    const int bh = blockIdx.y;
    const int row0 = blockIdx.x * QT;
    const int b = bh >> 4, h = bh & (H_ - 1);
    const size_t hoff = (size_t)bh * N_ * D_;
    const __nv_bfloat16 *qhp = g_qh + hoff, *qlp = g_ql + hoff;
    const __nv_bfloat16 *khp = g_kh + hoff, *klp = g_kl + hoff;
    const __nv_bfloat16 *vhp = g_vh + hoff, *vlp = g_vl + hoff;

    // stage Q tiles (hi & lo) into smem
    for (int idx = tid; idx < QT * 8; idx += 256) {
        int r = idx >> 3, cc = idx & 7;
        *(uint4*)(sm + A_QH + r * (VP * 2) + cc * 16) =
            *(const uint4*)(qhp + (size_t)(row0 + r) * D_ + cc * 8);
        *(uint4*)(sm + A_QL + r * (VP * 2) + cc * 16) =
            *(const uint4*)(qlp + (size_t)(row0 + r) * D_ + cc * 8);
    }
    __syncthreads();

    const int mrow0 = wid * 16;
    uint32_t qhf[4][4], qlf[4][4];
#pragma unroll
    for (int s = 0; s < 4; s++) {
        uint32_t ad = sb + A_QH + (mrow0 + (lane & 15)) * (VP * 2) + (s * 16 + (lane >> 4) * 8) * 2;
        ldsm4(qhf[s], ad);
        ldsm4(qlf[s], ad + (A_QL - A_QH));
    }

    // prefetch one 32-key tile: K/V hi/lo (4 x 32 rows x 8 chunks) + mask (128 x 4 chunks)
    auto prefetch = [&](int t, uint32_t bufb) {
        const int k0 = t * KT;
        const int rr = tid >> 3, cc = tid & 7;          // KV: row 0..31, chunk 0..7
        const uint32_t ro = rr * (VP * 2) + cc * 16;
        const size_t go = (size_t)(k0 + rr) * D_ + cc * 8;
        cp16(bufb + A_KH + ro, khp + go);
        cp16(bufb + A_KL + ro, klp + go);
        cp16(bufb + A_VH + ro, vhp + go);
        cp16(bufb + A_VL + ro, vlp + go);
#pragma unroll
        for (int j = 0; j < 2; j++) {
            int idx = tid + j * 256;
            int r = idx >> 2, c = idx & 3;              // mask: row 0..127, chunk 0..3
            cp16(bufb + A_MS + r * (MP * 2) + c * 16,
                 maskb + (size_t)(row0 + r) * N_ + k0 + c * 8);
        }
        cp_commit();
    };

    float o_acc[8][4] = {};
    float lsum0 = 0.f, lsum1 = 0.f;
    const int q2 = (lane & 3) * 2;
    const int r0l = mrow0 + (lane >> 2);

    prefetch(0, sb + A_BUF);

    for (int t = 0; t < N_ / KT; t++) {
        const uint32_t bufb = sb + A_BUF + (t & 1) * A_BUFSZ;
        if (t + 1 < N_ / KT) {
            prefetch(t + 1, sb + A_BUF + ((t + 1) & 1) * A_BUFSZ);
            cp_wait1();
        } else {
            cp_wait0();
        }
        __syncthreads();

        // ---- S' = Qh·Kh + Ql·Kh + Qh·Kl, term-major over 4 accumulators ----
        float s_acc[4][4] = {};
#pragma unroll
        for (int s = 0; s < 4; s++) {
            uint32_t khf[2][4], klf[2][4];
#pragma unroll
            for (int j = 0; j < 2; j++) {
                uint32_t kad = bufb + A_KH +
                    (j * 16 + ((lane >> 4) & 1) * 8 + (lane & 7)) * (VP * 2) +
                    (s * 16 + ((lane >> 3) & 1) * 8) * 2;
                ldsm4(khf[j], kad);
                ldsm4(klf[j], kad + (A_KL - A_KH));
            }
#pragma unroll
            for (int j = 0; j < 2; j++) {
                mma16816(s_acc[2 * j],     qhf[s], khf[j][0], khf[j][1]);
                mma16816(s_acc[2 * j + 1], qhf[s], khf[j][2], khf[j][3]);
            }
#pragma unroll
            for (int j = 0; j < 2; j++) {
                mma16816(s_acc[2 * j],     qlf[s], khf[j][0], khf[j][1]);
                mma16816(s_acc[2 * j + 1], qlf[s], khf[j][2], khf[j][3]);
            }
#pragma unroll
            for (int j = 0; j < 2; j++) {
                mma16816(s_acc[2 * j],     qhf[s], klf[j][0], klf[j][1]);
                mma16816(s_acc[2 * j + 1], qhf[s], klf[j][2], klf[j][3]);
            }
        }

        // ---- P = 2^(S'·mask - SHIFT2); accumulate row sums per-lane ----
        uint32_t pH[4], pH2[4], pL[4], pL2[4];
#pragma unroll
        for (int t4 = 0; t4 < 4; t4++) {
            uint32_t mw0 = *(uint32_t*)(sm + (bufb - sb) + A_MS + r0l * (MP * 2) + (t4 * 8 + q2) * 2);
            uint32_t mw1 = *(uint32_t*)(sm + (bufb - sb) + A_MS + (r0l + 8) * (MP * 2) + (t4 * 8 + q2) * 2);
            __nv_bfloat162 m0 = *(__nv_bfloat162*)&mw0;
            __nv_bfloat162 m1 = *(__nv_bfloat162*)&mw1;
            float p0 = fexp2(__fmaf_rn(s_acc[t4][0], __bfloat162float(m0.x), -SHIFT2_));
            float p1 = fexp2(__fmaf_rn(s_acc[t4][1], __bfloat162float(m0.y), -SHIFT2_));
            float p2 = fexp2(__fmaf_rn(s_acc[t4][2], __bfloat162float(m1.x), -SHIFT2_));
            float p3 = fexp2(__fmaf_rn(s_acc[t4][3], __bfloat162float(m1.y), -SHIFT2_));
            lsum0 += p0 + p1;
            lsum1 += p2 + p3;
            split_pack(p0, p1, pH[t4], pL[t4]);
            split_pack(p2, p3, pH2[t4], pL2[t4]);
        }

        // ---- O += Ph·Vh + Pl·Vh + Ph·Vl; V-frags in nd-pairs (reg cap) ----
#pragma unroll
        for (int kc = 0; kc < 2; kc++) {
            uint32_t ah[4]  = {pH[2 * kc], pH2[2 * kc], pH[2 * kc + 1], pH2[2 * kc + 1]};
            uint32_t alr[4] = {pL[2 * kc], pL2[2 * kc], pL[2 * kc + 1], pL2[2 * kc + 1]};
#pragma unroll
            for (int ndp = 0; ndp < 2; ndp++) {
                uint32_t vhf[2][4], vlf[2][4];
#pragma unroll
                for (int n2 = 0; n2 < 2; n2++) {
                    int nd = 2 * ndp + n2;
                    uint32_t vad = bufb + A_VH +
                        (kc * 16 + ((lane >> 3) & 1) * 8 + (lane & 7)) * (VP * 2) +
                        (nd * 16 + (lane >> 4) * 8) * 2;
                    ldsm4t(vhf[n2], vad);
                    ldsm4t(vlf[n2], vad + (A_VL - A_VH));
                }
#pragma unroll
                for (int n2 = 0; n2 < 2; n2++) {
                    int a0 = 2 * (2 * ndp + n2);
                    mma16816(o_acc[a0],     ah, vhf[n2][0], vhf[n2][1]);
                    mma16816(o_acc[a0 + 1], ah, vhf[n2][2], vhf[n2][3]);
                }
#pragma unroll
                for (int n2 = 0; n2 < 2; n2++) {
                    int a0 = 2 * (2 * ndp + n2);
                    mma16816(o_acc[a0],     alr, vhf[n2][0], vhf[n2][1]);
                    mma16816(o_acc[a0 + 1], alr, vhf[n2][2], vhf[n2][3]);
                }
#pragma unroll
                for (int n2 = 0; n2 < 2; n2++) {
                    int a0 = 2 * (2 * ndp + n2);
                    mma16816(o_acc[a0],     ah, vlf[n2][0], vlf[n2][1]);
                    mma16816(o_acc[a0 + 1], ah, vlf[n2][2], vlf[n2][3]);
                }
            }
        }
        __syncthreads();
    }

    lsum0 += __shfl_xor_sync(0xffffffffu, lsum0, 1);
    lsum0 += __shfl_xor_sync(0xffffffffu, lsum0, 2);
    lsum1 += __shfl_xor_sync(0xffffffffu, lsum1, 1);
    lsum1 += __shfl_xor_sync(0xffffffffu, lsum1, 2);

    float inv0 = 1.0f / lsum0, inv1 = 1.0f / lsum1;
    int n0 = row0 + r0l;
    size_t gr0 = ((size_t)b * N_ + n0) * C_;
    size_t gr1 = gr0 + (size_t)8 * C_;
#pragma unroll
    for (int t8 = 0; t8 < 8; t8++) {
        int col = h * D_ + t8 * 8 + q2;
        uint32_t hp, lp;
        split_pack(o_acc[t8][0] * inv0, o_acc[t8][1] * inv0, hp, lp);
        *(uint32_t*)(g_th + gr0 + col) = hp;
        *(uint32_t*)(g_tl + gr0 + col) = lp;
        split_pack(o_acc[t8][2] * inv1, o_acc[t8][3] * inv1, hp, lp);
        *(uint32_t*)(g_th + gr1 + col) = hp;
        *(uint32_t*)(g_tl + gr1 + col) = lp;
    }
}

// ---------------------------------------------------------------------------
extern "C" void kernel_launch(void* const* d_in, const int* in_sizes, int n_in,
                              void* d_out, int out_size) {
    const float* x      = (const float*)d_in[0];
    const float* w_qkv  = (const float*)d_in[1];
    const float* w_proj = (const float*)d_in[2];
    const float* b_proj = (const float*)d_in[3];
    const float* mask   = (const float*)d_in[4];
    float* out = (float*)d_out;
    (void)in_sizes; (void)n_in; (void)out_size;

    static __nv_bfloat16 *xh = nullptr, *xl, *wqh, *wql, *th, *tl, *wph, *wpl, *mb;
    static bool init_done = false;
    if (!init_done) {
        cudaFuncSetAttribute(attn_mma_kernel, cudaFuncAttributeMaxDynamicSharedMemorySize, ATT2_SMEM);
        cudaFuncSetAttribute(mm_mma_kernel, cudaFuncAttributeMaxDynamicSharedMemorySize, MM_SMEM);
        cudaGetSymbolAddress((void**)&xh,  g_xh);
        cudaGetSymbolAddress((void**)&xl,  g_xl);
        cudaGetSymbolAddress((void**)&wqh, g_wqh);
        cudaGetSymbolAddress((void**)&wql, g_wql);
        cudaGetSymbolAddress((void**)&th,  g_th);
        cudaGetSymbolAddress((void**)&tl,  g_tl);
        cudaGetSymbolAddress((void**)&wph, g_wph);
        cudaGetSymbolAddress((void**)&wpl, g_wpl);
        cudaGetSymbolAddress((void**)&mb,  g_maskb);
        init_done = true;
    }

    // Stage 0: fused fp32 -> hi/lo bf16 splits + mask conversion (one launch)
    preproc_kernel<<<QTOT / 256, 256>>>(x, w_qkv, w_proj, mask);

    // Stage 1: QKV projection (epilogue emits hi/lo bf16 q,k,v; q pre-scaled)
    mm_mma_kernel<<<dim3(3 * C_ / 128, (B_ * N_) / 128), 256, MM_SMEM>>>(
        xh, xl, wqh, wql, 0, nullptr, nullptr);

    // Stage 2: flash attention (KT=32, 2 CTAs/SM)
    attn_mma_kernel<<<dim3(N_ / QT, B_ * H_), 256, ATT2_SMEM>>>(mb);

    // Stage 3: output projection + bias
    mm_mma_kernel<<<dim3(C_ / 128, (B_ * N_) / 128), 256, MM_SMEM>>>(
        th, tl, wph, wpl, 1, b_proj, out);
}

// round 13
// speedup vs baseline: 1.1494x; 1.0380x over previous
#include <cuda_runtime.h>
#include <cuda_bf16.h>
#include <math.h>
#include <stdint.h>

#define B_ 2
#define N_ 2048
#define C_ 1024
#define H_ 16
#define D_ 64
#define QSCALE_ (0.125f * 1.4426950408889634f)   // SCALE * log2(e), folded into q
#define SHIFT2_ 11.541560327111708f              // 8 * log2(e)

// ---------------------------------------------------------------------------
// Scratch (allocation-free): all operands as separate hi/lo bf16 arrays
// ---------------------------------------------------------------------------
__device__ __nv_bfloat16 g_qh[(size_t)B_ * H_ * N_ * D_];
__device__ __nv_bfloat16 g_ql[(size_t)B_ * H_ * N_ * D_];
__device__ __nv_bfloat16 g_kh[(size_t)B_ * H_ * N_ * D_];
__device__ __nv_bfloat16 g_kl[(size_t)B_ * H_ * N_ * D_];
__device__ __nv_bfloat16 g_vh[(size_t)B_ * H_ * N_ * D_];
__device__ __nv_bfloat16 g_vl[(size_t)B_ * H_ * N_ * D_];
__device__ __nv_bfloat16 g_maskb[(size_t)N_ * N_];

__device__ __nv_bfloat16 g_xh [(size_t)(B_ * N_) * C_];
__device__ __nv_bfloat16 g_xl [(size_t)(B_ * N_) * C_];
__device__ __nv_bfloat16 g_wqh[(size_t)(3 * C_) * C_];
__device__ __nv_bfloat16 g_wql[(size_t)(3 * C_) * C_];
__device__ __nv_bfloat16 g_th [(size_t)(B_ * N_) * C_];
__device__ __nv_bfloat16 g_tl [(size_t)(B_ * N_) * C_];
__device__ __nv_bfloat16 g_wph[(size_t)C_ * C_];
__device__ __nv_bfloat16 g_wpl[(size_t)C_ * C_];

// ---------------------------------------------------------------------------
// PTX helpers
// ---------------------------------------------------------------------------
__device__ __forceinline__ uint32_t smem_u32(const void* p) {
    uint32_t a;
    asm("{ .reg .u64 t; cvta.to.shared.u64 t, %1; cvt.u32.u64 %0, t; }" : "=r"(a) : "l"(p));
    return a;
}
__device__ __forceinline__ void cp16(uint32_t dst, const void* src) {
    asm volatile("cp.async.cg.shared.global [%0], [%1], 16;" :: "r"(dst), "l"(src));
}
__device__ __forceinline__ void cp_commit() {
    asm volatile("cp.async.commit_group;");
}
__device__ __forceinline__ void cp_wait0() {
    asm volatile("cp.async.wait_group 0;");
}
__device__ __forceinline__ void cp_wait1() {
    asm volatile("cp.async.wait_group 1;");
}
__device__ __forceinline__ void ldsm4(uint32_t* r, uint32_t a) {
    asm volatile("ldmatrix.sync.aligned.m8n8.x4.shared.b16 {%0,%1,%2,%3}, [%4];"
                 : "=r"(r[0]), "=r"(r[1]), "=r"(r[2]), "=r"(r[3]) : "r"(a));
}
__device__ __forceinline__ void ldsm4t(uint32_t* r, uint32_t a) {
    asm volatile("ldmatrix.sync.aligned.m8n8.x4.trans.shared.b16 {%0,%1,%2,%3}, [%4];"
                 : "=r"(r[0]), "=r"(r[1]), "=r"(r[2]), "=r"(r[3]) : "r"(a));
}
__device__ __forceinline__ void mma16816(float* c, const uint32_t* a, uint32_t b0, uint32_t b1) {
    asm volatile(
        "mma.sync.aligned.m16n8k16.row.col.f32.bf16.bf16.f32 "
        "{%0,%1,%2,%3}, {%4,%5,%6,%7}, {%8,%9}, {%0,%1,%2,%3};"
        : "+f"(c[0]), "+f"(c[1]), "+f"(c[2]), "+f"(c[3])
        : "r"(a[0]), "r"(a[1]), "r"(a[2]), "r"(a[3]), "r"(b0), "r"(b1));
}
__device__ __forceinline__ float fexp2(float x) {
    float r;
    asm("ex2.approx.f32 %0, %1;" : "=f"(r) : "f"(x));
    return r;
}
__device__ __forceinline__ void split_pack(float a, float b, uint32_t& hp, uint32_t& lp) {
    __nv_bfloat16 ha = __float2bfloat16(a), hb = __float2bfloat16(b);
    __nv_bfloat16 la = __float2bfloat16(a - __bfloat162float(ha));
    __nv_bfloat16 lb = __float2bfloat16(b - __bfloat162float(hb));
    __nv_bfloat162 hv = {ha, hb}, lv = {la, lb};
    hp = *(uint32_t*)&hv;
    lp = *(uint32_t*)&lv;
}

// ---------------------------------------------------------------------------
// Fused preprocessing: x/w_qkv/w_proj hi/lo splits + mask bf16 conversion.
// ---------------------------------------------------------------------------
#define QX  (B_ * N_ * C_ / 4)
#define QWQ (3 * C_ * C_ / 4)
#define QWP (C_ * C_ / 4)
#define QMK (N_ * N_ / 4)
#define QTOT (QX + QWQ + QWP + QMK)

__device__ __forceinline__ void split_quad(const float* __restrict__ src,
                                           __nv_bfloat16* __restrict__ dh,
                                           __nv_bfloat16* __restrict__ dl, int i4) {
    float4 a = ((const float4*)src)[i4];
    __nv_bfloat16 h0 = __float2bfloat16(a.x), h1 = __float2bfloat16(a.y);
    __nv_bfloat16 h2 = __float2bfloat16(a.z), h3 = __float2bfloat16(a.w);
    __nv_bfloat16 l0 = __float2bfloat16(a.x - __bfloat162float(h0));
    __nv_bfloat16 l1 = __float2bfloat16(a.y - __bfloat162float(h1));
    __nv_bfloat16 l2 = __float2bfloat16(a.z - __bfloat162float(h2));
    __nv_bfloat16 l3 = __float2bfloat16(a.w - __bfloat162float(h3));
    __nv_bfloat162 hA = {h0, h1}, hB = {h2, h3};
    __nv_bfloat162 lA = {l0, l1}, lB = {l2, l3};
    ((__nv_bfloat162*)dh)[2 * i4]     = hA;
    ((__nv_bfloat162*)dh)[2 * i4 + 1] = hB;
    ((__nv_bfloat162*)dl)[2 * i4]     = lA;
    ((__nv_bfloat162*)dl)[2 * i4 + 1] = lB;
}

__global__ __launch_bounds__(256) void preproc_kernel(const float* __restrict__ x,
                                                      const float* __restrict__ wqkv,
                                                      const float* __restrict__ wproj,
                                                      const float* __restrict__ mask) {
    int i = blockIdx.x * 256 + threadIdx.x;
    if (i < QX) {
        split_quad(x, g_xh, g_xl, i);
    } else if (i < QX + QWQ) {
        split_quad(wqkv, g_wqh, g_wql, i - QX);
    } else if (i < QX + QWQ + QWP) {
        split_quad(wproj, g_wph, g_wpl, i - QX - QWQ);
    } else {
        int j = i - QX - QWQ - QWP;
        float4 v = ((const float4*)mask)[j];
        __nv_bfloat162 p0 = {__float2bfloat16(v.x), __float2bfloat16(v.y)};
        __nv_bfloat162 p1 = {__float2bfloat16(v.z), __float2bfloat16(v.w)};
        ((__nv_bfloat162*)g_maskb)[2 * j]     = p0;
        ((__nv_bfloat162*)g_maskb)[2 * j + 1] = p1;
    }
}

// ---------------------------------------------------------------------------
// mma.sync GEMM: CTA 128x128, 512 threads, 16 warps (4M x 4N), warp 32x32.
// BK=32 double-buffered, term-major MMA ordering. 2 CTAs/SM target (8 w/SMSP).
// mode 0: split-scatter into g_{q,k,v}{h,l} (q pre-scaled).  mode 1: +bias.
// ---------------------------------------------------------------------------
#define PITCH 40
#define GK 1024
#define MITERS (GK / 32)         // 32
#define T_AH 0
#define T_AL (128 * PITCH)
#define T_BH (2 * 128 * PITCH)
#define T_BL (3 * 128 * PITCH)
#define MMBUF (4 * 128 * PITCH)              // 20480 elems = 40960 B
#define MM_SMEM (2 * MMBUF * 2)              // 81920 B

__global__ __launch_bounds__(512, 2) void mm_mma_kernel(const __nv_bfloat16* __restrict__ Ah,
                                                        const __nv_bfloat16* __restrict__ Al,
                                                        const __nv_bfloat16* __restrict__ Bh,
                                                        const __nv_bfloat16* __restrict__ Bl,
                                                        int mode,
                                                        const float* __restrict__ bias,
                                                        float* __restrict__ outp) {
    extern __shared__ __nv_bfloat16 smb[];

    const int tid = threadIdx.x;
    const int wid = tid >> 5;
    const int lane = tid & 31;
    const int brow = blockIdx.y * 128;
    const int bcol = blockIdx.x * 128;
    const int mbase = (wid >> 2) * 32;      // 4 M-warps
    const int nbase = (wid & 3) * 32;       // 4 N-warps

    const uint32_t sbase = smem_u32(smb);

    // loads: 4 tiles x 128 rows x 4 chunks = 2048 chunks; 512 threads x 4 each
    const int lr0 = tid >> 2;               // row 0..127
    const int lq0 = tid & 3;                // chunk 0..3

    auto load_tile = [&](int kt, int buf) {
        const int k0 = kt * 32;
        const size_t go = (size_t)(brow + lr0) * GK + k0 + lq0 * 8;
        const size_t gob = (size_t)(bcol + lr0) * GK + k0 + lq0 * 8;
        uint32_t sb = sbase + buf * (MMBUF * 2) + (lr0 * PITCH) * 2 + lq0 * 16;
        cp16(sb + T_AH * 2, Ah + go);
        cp16(sb + T_AL * 2, Al + go);
        cp16(sb + T_BH * 2, Bh + gob);
        cp16(sb + T_BL * 2, Bl + gob);
        cp_commit();
    };

    float acc[2][4][4] = {};                // 2 m16 x 4 n8 x 4

    load_tile(0, 0);
    cp_wait0();
    __syncthreads();

    for (int kt = 0; kt < MITERS; kt++) {
        const int buf = kt & 1;
        const uint32_t sb = sbase + buf * (MMBUF * 2);
        if (kt + 1 < MITERS) load_tile(kt + 1, buf ^ 1);

#pragma unroll
        for (int s = 0; s < 2; s++) {
            // B fragments (hi & lo) for both n16 halves
            uint32_t bh[2][4], bl[2][4];
#pragma unroll
            for (int j = 0; j < 2; j++) {
                int row = nbase + j * 16 + ((lane >> 4) & 1) * 8 + (lane & 7);
                int col = s * 16 + ((lane >> 3) & 1) * 8;
                uint32_t ba = sb + (row * PITCH + col) * 2;
                ldsm4(bh[j], ba + T_BH * 2);
                ldsm4(bl[j], ba + T_BL * 2);
            }
            // A fragments (hi & lo) for both m16 halves
            uint32_t ah[2][4], al[2][4];
#pragma unroll
            for (int i = 0; i < 2; i++) {
                uint32_t aa = sb +
                    ((mbase + i * 16 + (lane & 15)) * PITCH + s * 16 + (lane >> 4) * 8) * 2;
                ldsm4(ah[i], aa + T_AH * 2);
                ldsm4(al[i], aa + T_AL * 2);
            }
            // term 1: Ah·Bh (8 MMAs over 8 distinct accs)
#pragma unroll
            for (int i = 0; i < 2; i++)
#pragma unroll
                for (int j = 0; j < 2; j++) {
                    mma16816(acc[i][2 * j],     ah[i], bh[j][0], bh[j][1]);
                    mma16816(acc[i][2 * j + 1], ah[i], bh[j][2], bh[j][3]);
                }
            // term 2: Al·Bh
#pragma unroll
            for (int i = 0; i < 2; i++)
#pragma unroll
                for (int j = 0; j < 2; j++) {
                    mma16816(acc[i][2 * j],     al[i], bh[j][0], bh[j][1]);
                    mma16816(acc[i][2 * j + 1], al[i], bh[j][2], bh[j][3]);
                }
            // term 3: Ah·Bl
#pragma unroll
            for (int i = 0; i < 2; i++)
#pragma unroll
                for (int j = 0; j < 2; j++) {
                    mma16816(acc[i][2 * j],     ah[i], bl[j][0], bl[j][1]);
                    mma16816(acc[i][2 * j + 1], ah[i], bl[j][2], bl[j][3]);
                }
        }

        if (kt + 1 < MITERS) cp_wait0();
        __syncthreads();
    }

    const int r0 = brow + mbase + (lane >> 2);
    const int cq = (lane & 3) * 2;
#pragma unroll
    for (int i = 0; i < 2; i++) {
#pragma unroll
        for (int jj = 0; jj < 4; jj++) {
            const float* c = acc[i][jj];
            int gc = bcol + nbase + jj * 8 + cq;
#pragma unroll
            for (int hrow = 0; hrow < 2; hrow++) {
                int gi = r0 + i * 16 + hrow * 8;
                float vx = c[hrow * 2 + 0], vy = c[hrow * 2 + 1];
                if (mode == 0) {
                    int bb = gi >> 11;
                    int nseq = gi & (N_ - 1);
                    int three = gc >> 10;
                    int h = (gc >> 6) & (H_ - 1);
                    int d = gc & (D_ - 1);
                    if (three == 0) { vx *= QSCALE_; vy *= QSCALE_; }
                    uint32_t hp, lp;
                    split_pack(vx, vy, hp, lp);
                    __nv_bfloat16 *hd, *ld;
                    if (three == 0)      { hd = g_qh; ld = g_ql; }
                    else if (three == 1) { hd = g_kh; ld = g_kl; }
                    else                 { hd = g_vh; ld = g_vl; }
                    size_t off = (((size_t)bb * H_ + h) * N_ + nseq) * D_ + d;
                    *(uint32_t*)(hd + off) = hp;
                    *(uint32_t*)(ld + off) = lp;
                } else {
                    float2 val = {vx + bias[gc], vy + bias[gc + 1]};
                    *(float2*)&outp[(size_t)gi * C_ + gc] = val;
                }
            }
        }
    }
}

// ---------------------------------------------------------------------------
// Flash attention (R12, unchanged — protected win): KT=32, 2 CTAs/SM,
// fixed-shift base-2 softmax, 3-term splits, term-major MMA ordering.
// ---------------------------------------------------------------------------
#define QT 128
#define KT 32
#define VP 72
#define MP 40
#define A_QH 0
#define A_QL (QT * VP * 2)
#define A_BUF (2 * QT * VP * 2)
#define A_KH 0
#define A_KL (KT * VP * 2)
#define A_VH (2 * KT * VP * 2)
#define A_VL (3 * KT * VP * 2)
#define A_MS (4 * KT * VP * 2)
#define A_BUFSZ (4 * KT * VP * 2 + QT * MP * 2)   // 28672
#define ATT2_SMEM (A_BUF + 2 * A_BUFSZ)           // 94208 -> 2 CTAs/SM

__global__ __launch_bounds__(256, 2) void attn_mma_kernel(const __nv_bfloat16* __restrict__ maskb) {
    extern __shared__ char sm[];
    const uint32_t sb = smem_u32(sm);
    const int tid = threadIdx.x, wid = tid >> 5, lane = tid & 31;
    const int bh = blockIdx.y;
    const int row0 = blockIdx.x * QT;
    const int b = bh >> 4, h = bh & (H_ - 1);
    const size_t hoff = (size_t)bh * N_ * D_;
    const __nv_bfloat16 *qhp = g_qh + hoff, *qlp = g_ql + hoff;
    const __nv_bfloat16 *khp = g_kh + hoff, *klp = g_kl + hoff;
    const __nv_bfloat16 *vhp = g_vh + hoff, *vlp = g_vl + hoff;

    for (int idx = tid; idx < QT * 8; idx += 256) {
        int r = idx >> 3, cc = idx & 7;
        *(uint4*)(sm + A_QH + r * (VP * 2) + cc * 16) =
            *(const uint4*)(qhp + (size_t)(row0 + r) * D_ + cc * 8);
        *(uint4*)(sm + A_QL + r * (VP * 2) + cc * 16) =
            *(const uint4*)(qlp + (size_t)(row0 + r) * D_ + cc * 8);
    }
    __syncthreads();

    const int mrow0 = wid * 16;
    uint32_t qhf[4][4], qlf[4][4];
#pragma unroll
    for (int s = 0; s < 4; s++) {
        uint32_t ad = sb + A_QH + (mrow0 + (lane & 15)) * (VP * 2) + (s * 16 + (lane >> 4) * 8) * 2;
        ldsm4(qhf[s], ad);
        ldsm4(qlf[s], ad + (A_QL - A_QH));
    }

    auto prefetch = [&](int t, uint32_t bufb) {
        const int k0 = t * KT;
        const int rr = tid >> 3, cc = tid & 7;
        const uint32_t ro = rr * (VP * 2) + cc * 16;
        const size_t go = (size_t)(k0 + rr) * D_ + cc * 8;
        cp16(bufb + A_KH + ro, khp + go);
        cp16(bufb + A_KL + ro, klp + go);
        cp16(bufb + A_VH + ro, vhp + go);
        cp16(bufb + A_VL + ro, vlp + go);
#pragma unroll
        for (int j = 0; j < 2; j++) {
            int idx = tid + j * 256;
            int r = idx >> 2, c = idx & 3;
            cp16(bufb + A_MS + r * (MP * 2) + c * 16,
                 maskb + (size_t)(row0 + r) * N_ + k0 + c * 8);
        }
        cp_commit();
    };

    float o_acc[8][4] = {};
    float lsum0 = 0.f, lsum1 = 0.f;
    const int q2 = (lane & 3) * 2;
    const int r0l = mrow0 + (lane >> 2);

    prefetch(0, sb + A_BUF);

    for (int t = 0; t < N_ / KT; t++) {
        const uint32_t bufb = sb + A_BUF + (t & 1) * A_BUFSZ;
        if (t + 1 < N_ / KT) {
            prefetch(t + 1, sb + A_BUF + ((t + 1) & 1) * A_BUFSZ);
            cp_wait1();
        } else {
            cp_wait0();
        }
        __syncthreads();

        float s_acc[4][4] = {};
#pragma unroll
        for (int s = 0; s < 4; s++) {
            uint32_t khf[2][4], klf[2][4];
#pragma unroll
            for (int j = 0; j < 2; j++) {
                uint32_t kad = bufb + A_KH +
                    (j * 16 + ((lane >> 4) & 1) * 8 + (lane & 7)) * (VP * 2) +
                    (s * 16 + ((lane >> 3) & 1) * 8) * 2;
                ldsm4(khf[j], kad);
                ldsm4(klf[j], kad + (A_KL - A_KH));
            }
#pragma unroll
            for (int j = 0; j < 2; j++) {
                mma16816(s_acc[2 * j],     qhf[s], khf[j][0], khf[j][1]);
                mma16816(s_acc[2 * j + 1], qhf[s], khf[j][2], khf[j][3]);
            }
#pragma unroll
            for (int j = 0; j < 2; j++) {
                mma16816(s_acc[2 * j],     qlf[s], khf[j][0], khf[j][1]);
                mma16816(s_acc[2 * j + 1], qlf[s], khf[j][2], khf[j][3]);
            }
#pragma unroll
            for (int j = 0; j < 2; j++) {
                mma16816(s_acc[2 * j],     qhf[s], klf[j][0], klf[j][1]);
                mma16816(s_acc[2 * j + 1], qhf[s], klf[j][2], klf[j][3]);
            }
        }

        uint32_t pH[4], pH2[4], pL[4], pL2[4];
#pragma unroll
        for (int t4 = 0; t4 < 4; t4++) {
            uint32_t mw0 = *(uint32_t*)(sm + (bufb - sb) + A_MS + r0l * (MP * 2) + (t4 * 8 + q2) * 2);
            uint32_t mw1 = *(uint32_t*)(sm + (bufb - sb) + A_MS + (r0l + 8) * (MP * 2) + (t4 * 8 + q2) * 2);
            __nv_bfloat162 m0 = *(__nv_bfloat162*)&mw0;
            __nv_bfloat162 m1 = *(__nv_bfloat162*)&mw1;
            float p0 = fexp2(__fmaf_rn(s_acc[t4][0], __bfloat162float(m0.x), -SHIFT2_));
            float p1 = fexp2(__fmaf_rn(s_acc[t4][1], __bfloat162float(m0.y), -SHIFT2_));
            float p2 = fexp2(__fmaf_rn(s_acc[t4][2], __bfloat162float(m1.x), -SHIFT2_));
            float p3 = fexp2(__fmaf_rn(s_acc[t4][3], __bfloat162float(m1.y), -SHIFT2_));
            lsum0 += p0 + p1;
            lsum1 += p2 + p3;
            split_pack(p0, p1, pH[t4], pL[t4]);
            split_pack(p2, p3, pH2[t4], pL2[t4]);
        }

#pragma unroll
        for (int kc = 0; kc < 2; kc++) {
            uint32_t ah[4]  = {pH[2 * kc], pH2[2 * kc], pH[2 * kc + 1], pH2[2 * kc + 1]};
            uint32_t alr[4] = {pL[2 * kc], pL2[2 * kc], pL[2 * kc + 1], pL2[2 * kc + 1]};
#pragma unroll
            for (int ndp = 0; ndp < 2; ndp++) {
                uint32_t vhf[2][4], vlf[2][4];
#pragma unroll
                for (int n2 = 0; n2 < 2; n2++) {
                    int nd = 2 * ndp + n2;
                    uint32_t vad = bufb + A_VH +
                        (kc * 16 + ((lane >> 3) & 1) * 8 + (lane & 7)) * (VP * 2) +
                        (nd * 16 + (lane >> 4) * 8) * 2;
                    ldsm4t(vhf[n2], vad);
                    ldsm4t(vlf[n2], vad + (A_VL - A_VH));
                }
#pragma unroll
                for (int n2 = 0; n2 < 2; n2++) {
                    int a0 = 2 * (2 * ndp + n2);
                    mma16816(o_acc[a0],     ah, vhf[n2][0], vhf[n2][1]);
                    mma16816(o_acc[a0 + 1], ah, vhf[n2][2], vhf[n2][3]);
                }
#pragma unroll
                for (int n2 = 0; n2 < 2; n2++) {
                    int a0 = 2 * (2 * ndp + n2);
                    mma16816(o_acc[a0],     alr, vhf[n2][0], vhf[n2][1]);
                    mma16816(o_acc[a0 + 1], alr, vhf[n2][2], vhf[n2][3]);
                }
#pragma unroll
                for (int n2 = 0; n2 < 2; n2++) {
                    int a0 = 2 * (2 * ndp + n2);
                    mma16816(o_acc[a0],     ah, vlf[n2][0], vlf[n2][1]);
                    mma16816(o_acc[a0 + 1], ah, vlf[n2][2], vlf[n2][3]);
                }
            }
        }
        __syncthreads();
    }

    lsum0 += __shfl_xor_sync(0xffffffffu, lsum0, 1);
    lsum0 += __shfl_xor_sync(0xffffffffu, lsum0, 2);
    lsum1 += __shfl_xor_sync(0xffffffffu, lsum1, 1);
    lsum1 += __shfl_xor_sync(0xffffffffu, lsum1, 2);

    float inv0 = 1.0f / lsum0, inv1 = 1.0f / lsum1;
    int n0 = row0 + r0l;
    size_t gr0 = ((size_t)b * N_ + n0) * C_;
    size_t gr1 = gr0 + (size_t)8 * C_;
#pragma unroll
    for (int t8 = 0; t8 < 8; t8++) {
        int col = h * D_ + t8 * 8 + q2;
        uint32_t hp, lp;
        split_pack(o_acc[t8][0] * inv0, o_acc[t8][1] * inv0, hp, lp);
        *(uint32_t*)(g_th + gr0 + col) = hp;
        *(uint32_t*)(g_tl + gr0 + col) = lp;
        split_pack(o_acc[t8][2] * inv1, o_acc[t8][3] * inv1, hp, lp);
        *(uint32_t*)(g_th + gr1 + col) = hp;
        *(uint32_t*)(g_tl + gr1 + col) = lp;
    }
}

// ---------------------------------------------------------------------------
extern "C" void kernel_launch(void* const* d_in, const int* in_sizes, int n_in,
                              void* d_out, int out_size) {
    const float* x      = (const float*)d_in[0];
    const float* w_qkv  = (const float*)d_in[1];
    const float* w_proj = (const float*)d_in[2];
    const float* b_proj = (const float*)d_in[3];
    const float* mask   = (const float*)d_in[4];
    float* out = (float*)d_out;
    (void)in_sizes; (void)n_in; (void)out_size;

    static __nv_bfloat16 *xh = nullptr, *xl, *wqh, *wql, *th, *tl, *wph, *wpl, *mb;
    static bool init_done = false;
    if (!init_done) {
        cudaFuncSetAttribute(attn_mma_kernel, cudaFuncAttributeMaxDynamicSharedMemorySize, ATT2_SMEM);
        cudaFuncSetAttribute(mm_mma_kernel, cudaFuncAttributeMaxDynamicSharedMemorySize, MM_SMEM);
        cudaGetSymbolAddress((void**)&xh,  g_xh);
        cudaGetSymbolAddress((void**)&xl,  g_xl);
        cudaGetSymbolAddress((void**)&wqh, g_wqh);
        cudaGetSymbolAddress((void**)&wql, g_wql);
        cudaGetSymbolAddress((void**)&th,  g_th);
        cudaGetSymbolAddress((void**)&tl,  g_tl);
        cudaGetSymbolAddress((void**)&wph, g_wph);
        cudaGetSymbolAddress((void**)&wpl, g_wpl);
        cudaGetSymbolAddress((void**)&mb,  g_maskb);
        init_done = true;
    }

    // Stage 0: fused fp32 -> hi/lo bf16 splits + mask conversion (one launch)
    preproc_kernel<<<QTOT / 256, 256>>>(x, w_qkv, w_proj, mask);

    // Stage 1: QKV projection (512 threads/CTA)
    mm_mma_kernel<<<dim3(3 * C_ / 128, (B_ * N_) / 128), 512, MM_SMEM>>>(
        xh, xl, wqh, wql, 0, nullptr, nullptr);

    // Stage 2: flash attention (KT=32, 2 CTAs/SM)
    attn_mma_kernel<<<dim3(N_ / QT, B_ * H_), 256, ATT2_SMEM>>>(mb);

    // Stage 3: output projection + bias (512 threads/CTA)
    mm_mma_kernel<<<dim3(C_ / 128, (B_ * N_) / 128), 512, MM_SMEM>>>(
        th, tl, wph, wpl, 1, b_proj, out);
}